// round 3
// baseline (speedup 1.0000x reference)
#include <cuda_runtime.h>

#define NB  4
#define NS  2048
#define ND  512
#define NH  8
#define NHD 64
#define NROWS (NB*NS)   // 8192

// Scratch (device globals — no allocation inside kernel_launch)
__device__ float g_Q[NB*NH*NS*NHD];   // [B,H,S,64]
__device__ float g_K[NB*NH*NS*NHD];
__device__ float g_V[NB*NH*NS*NHD];
__device__ float g_O[NB*NS*ND];       // [B,S,D] merged attention output

// ---------------------------------------------------------------------------
// Fused QKV projection: C = A[8192,512] @ W[512,512], output head-split.
// grid = (8, 128, 3), block = 256. 64x64 C tile, 16-deep k tiles, 4x4 microtile.
// ---------------------------------------------------------------------------
__global__ __launch_bounds__(256) void proj_kernel(
    const float* __restrict__ X, const float* __restrict__ Y, const float* __restrict__ Z,
    const float* __restrict__ Wq, const float* __restrict__ Wk, const float* __restrict__ Wo)
{
    __shared__ float As[16][64];   // [k][row]  (k-major so reads are float4 on rows)
    __shared__ float Bs[16][64];   // [k][col]

    const float* A; const float* W; float* Out;
    if (blockIdx.z == 0)      { A = X; W = Wq; Out = g_Q; }
    else if (blockIdx.z == 1) { A = Y; W = Wk; Out = g_K; }
    else                      { A = Z; W = Wo; Out = g_V; }   // NOTE: V uses Wo (faithful to ref)

    const int t  = threadIdx.x;
    const int tx = t & 15;          // col group 0..15
    const int ty = t >> 4;          // row group 0..15
    const int row0 = blockIdx.y * 64;
    const int col0 = blockIdx.x * 64;

    const int lar = t & 63;         // A-tile row this thread loads
    const int lac = (t >> 6) * 4;   // A-tile col group (0,4,8,12)
    const int lbr = t >> 4;         // W-tile row 0..15
    const int lbc = (t & 15) * 4;   // W-tile col group

    float acc[4][4] = {};

    for (int k0 = 0; k0 < ND; k0 += 16) {
        float4 av = *(const float4*)&A[(row0 + lar) * ND + k0 + lac];
        As[lac + 0][lar] = av.x;
        As[lac + 1][lar] = av.y;
        As[lac + 2][lar] = av.z;
        As[lac + 3][lar] = av.w;
        *(float4*)&Bs[lbr][lbc] = *(const float4*)&W[(k0 + lbr) * ND + col0 + lbc];
        __syncthreads();

        #pragma unroll
        for (int kk = 0; kk < 16; kk++) {
            float4 a = *(const float4*)&As[kk][ty * 4];
            float4 b = *(const float4*)&Bs[kk][tx * 4];
            acc[0][0] += a.x*b.x; acc[0][1] += a.x*b.y; acc[0][2] += a.x*b.z; acc[0][3] += a.x*b.w;
            acc[1][0] += a.y*b.x; acc[1][1] += a.y*b.y; acc[1][2] += a.y*b.z; acc[1][3] += a.y*b.w;
            acc[2][0] += a.z*b.x; acc[2][1] += a.z*b.y; acc[2][2] += a.z*b.z; acc[2][3] += a.z*b.w;
            acc[3][0] += a.w*b.x; acc[3][1] += a.w*b.y; acc[3][2] += a.w*b.z; acc[3][3] += a.w*b.w;
        }
        __syncthreads();
    }

    // One 64-wide column tile == exactly one head (512/64 == 8 == NH).
    const int h = blockIdx.x;
    #pragma unroll
    for (int i = 0; i < 4; i++) {
        int r = row0 + ty * 4 + i;
        int b = r >> 11;        // r / 2048
        int s = r & 2047;
        float4 v = make_float4(acc[i][0], acc[i][1], acc[i][2], acc[i][3]);
        *(float4*)&Out[(((size_t)(b * NH + h) * NS) + s) * NHD + tx * 4] = v;
    }
}

// ---------------------------------------------------------------------------
// Flash-style attention for one (b,h) and one 64-row q tile.
// grid = (32, 32), block = 256. ReLU(score/8) -> online softmax -> P@V.
// Static smem exactly 48KB: Qt(16K) + KtPs(16K, K tile aliased with P tile) + Vs(16K).
// ---------------------------------------------------------------------------
__global__ __launch_bounds__(256) void attn_kernel()
{
    __shared__ float Qt[64][64];    // [d][qrow]   (d-major -> float4 reads on rows)
    __shared__ float KtPs[64][64];  // phase 1: K [d][kcol]; phase 2: P [qrow][kcol]
    __shared__ float Vs[64][64];    // [kcol][d]

    const int t  = threadIdx.x;
    const int tx = t & 15;
    const int ty = t >> 4;
    const int bh = blockIdx.y;
    const int q0 = blockIdx.x * 64;

    const float* Qg = g_Q + (size_t)bh * NS * NHD;
    const float* Kg = g_K + (size_t)bh * NS * NHD;
    const float* Vg = g_V + (size_t)bh * NS * NHD;

    const int lr = t & 63;          // tile row this thread loads
    const int lc = (t >> 6) * 16;   // 16-col span

    // Load Q tile transposed (d-major). Bank-conflict-free: lanes hit distinct banks (lr).
    #pragma unroll
    for (int c4 = 0; c4 < 4; c4++) {
        int col = lc + c4 * 4;
        float4 v = *(const float4*)&Qg[(q0 + lr) * NHD + col];
        Qt[col + 0][lr] = v.x;
        Qt[col + 1][lr] = v.y;
        Qt[col + 2][lr] = v.z;
        Qt[col + 3][lr] = v.w;
    }

    float m[4], l[4], o[4][4];
    #pragma unroll
    for (int i = 0; i < 4; i++) {
        m[i] = 0.f; l[i] = 0.f;               // scores >= 0 post-ReLU, so m=0 init is exact
        #pragma unroll
        for (int j = 0; j < 4; j++) o[i][j] = 0.f;
    }

    for (int j0 = 0; j0 < NS; j0 += 64) {
        __syncthreads();   // previous tile's P@V (reads Vs/KtPs) must be done

        // Load K (transposed, d-major) and V (row-major) tiles
        #pragma unroll
        for (int c4 = 0; c4 < 4; c4++) {
            int col = lc + c4 * 4;
            float4 kv = *(const float4*)&Kg[(j0 + lr) * NHD + col];
            KtPs[col + 0][lr] = kv.x;
            KtPs[col + 1][lr] = kv.y;
            KtPs[col + 2][lr] = kv.z;
            KtPs[col + 3][lr] = kv.w;
            *(float4*)&Vs[lr][col] = *(const float4*)&Vg[(j0 + lr) * NHD + col];
        }
        __syncthreads();

        // S = Q @ K^T  (64x64x64)
        float s[4][4] = {};
        #pragma unroll
        for (int kk = 0; kk < 64; kk++) {
            float4 a = *(const float4*)&Qt[kk][ty * 4];
            float4 b = *(const float4*)&KtPs[kk][tx * 4];
            s[0][0] += a.x*b.x; s[0][1] += a.x*b.y; s[0][2] += a.x*b.z; s[0][3] += a.x*b.w;
            s[1][0] += a.y*b.x; s[1][1] += a.y*b.y; s[1][2] += a.y*b.z; s[1][3] += a.y*b.w;
            s[2][0] += a.z*b.x; s[2][1] += a.z*b.y; s[2][2] += a.z*b.z; s[2][3] += a.z*b.w;
            s[3][0] += a.w*b.x; s[3][1] += a.w*b.y; s[3][2] += a.w*b.z; s[3][3] += a.w*b.w;
        }

        // scale (1/sqrt(64) = 0.125 exact) + ReLU + online softmax update
        #pragma unroll
        for (int i = 0; i < 4; i++) {
            #pragma unroll
            for (int j = 0; j < 4; j++)
                s[i][j] = fmaxf(s[i][j] * 0.125f, 0.f);

            float mx = fmaxf(fmaxf(s[i][0], s[i][1]), fmaxf(s[i][2], s[i][3]));
            mx = fmaxf(mx, __shfl_xor_sync(0xffffffffu, mx, 1));
            mx = fmaxf(mx, __shfl_xor_sync(0xffffffffu, mx, 2));
            mx = fmaxf(mx, __shfl_xor_sync(0xffffffffu, mx, 4));
            mx = fmaxf(mx, __shfl_xor_sync(0xffffffffu, mx, 8));

            float mn    = fmaxf(m[i], mx);
            float alpha = __expf(m[i] - mn);
            float rsum  = 0.f;
            #pragma unroll
            for (int j = 0; j < 4; j++) {
                float p = __expf(s[i][j] - mn);
                s[i][j] = p;
                rsum += p;
            }
            rsum += __shfl_xor_sync(0xffffffffu, rsum, 1);
            rsum += __shfl_xor_sync(0xffffffffu, rsum, 2);
            rsum += __shfl_xor_sync(0xffffffffu, rsum, 4);
            rsum += __shfl_xor_sync(0xffffffffu, rsum, 8);

            l[i] = l[i] * alpha + rsum;
            m[i] = mn;
            #pragma unroll
            for (int j = 0; j < 4; j++) o[i][j] *= alpha;
        }

        __syncthreads();   // everyone done reading K tile before P overwrites it

        // Stage P into smem (aliases K tile)
        #pragma unroll
        for (int i = 0; i < 4; i++)
            *(float4*)&KtPs[ty * 4 + i][tx * 4] =
                make_float4(s[i][0], s[i][1], s[i][2], s[i][3]);
        __syncthreads();

        // O += P @ V  (64x64x64)
        #pragma unroll
        for (int j = 0; j < 64; j++) {
            float4 bv = *(const float4*)&Vs[j][tx * 4];
            float a0 = KtPs[ty * 4 + 0][j];
            float a1 = KtPs[ty * 4 + 1][j];
            float a2 = KtPs[ty * 4 + 2][j];
            float a3 = KtPs[ty * 4 + 3][j];
            o[0][0] += a0*bv.x; o[0][1] += a0*bv.y; o[0][2] += a0*bv.z; o[0][3] += a0*bv.w;
            o[1][0] += a1*bv.x; o[1][1] += a1*bv.y; o[1][2] += a1*bv.z; o[1][3] += a1*bv.w;
            o[2][0] += a2*bv.x; o[2][1] += a2*bv.y; o[2][2] += a2*bv.z; o[2][3] += a2*bv.w;
            o[3][0] += a3*bv.x; o[3][1] += a3*bv.y; o[3][2] += a3*bv.z; o[3][3] += a3*bv.w;
        }
    }

    // Normalize and write merged [B,S,D]
    const int b = bh >> 3;
    const int h = bh & 7;
    #pragma unroll
    for (int i = 0; i < 4; i++) {
        float inv = 1.f / l[i];
        int srow = q0 + ty * 4 + i;
        float4 v = make_float4(o[i][0]*inv, o[i][1]*inv, o[i][2]*inv, o[i][3]*inv);
        *(float4*)&g_O[((size_t)(b * NS + srow)) * ND + h * NHD + tx * 4] = v;
    }
}

// ---------------------------------------------------------------------------
// Output projection: out = g_O[8192,512] @ Wo[512,512], plain row-major out.
// grid = (8, 128), block = 256.
// ---------------------------------------------------------------------------
__global__ __launch_bounds__(256) void oproj_kernel(
    const float* __restrict__ Wo, float* __restrict__ out)
{
    __shared__ float As[16][64];
    __shared__ float Bs[16][64];

    const int t  = threadIdx.x;
    const int tx = t & 15;
    const int ty = t >> 4;
    const int row0 = blockIdx.y * 64;
    const int col0 = blockIdx.x * 64;

    const int lar = t & 63;
    const int lac = (t >> 6) * 4;
    const int lbr = t >> 4;
    const int lbc = (t & 15) * 4;

    float acc[4][4] = {};

    for (int k0 = 0; k0 < ND; k0 += 16) {
        float4 av = *(const float4*)&g_O[(size_t)(row0 + lar) * ND + k0 + lac];
        As[lac + 0][lar] = av.x;
        As[lac + 1][lar] = av.y;
        As[lac + 2][lar] = av.z;
        As[lac + 3][lar] = av.w;
        *(float4*)&Bs[lbr][lbc] = *(const float4*)&Wo[(k0 + lbr) * ND + col0 + lbc];
        __syncthreads();

        #pragma unroll
        for (int kk = 0; kk < 16; kk++) {
            float4 a = *(const float4*)&As[kk][ty * 4];
            float4 b = *(const float4*)&Bs[kk][tx * 4];
            acc[0][0] += a.x*b.x; acc[0][1] += a.x*b.y; acc[0][2] += a.x*b.z; acc[0][3] += a.x*b.w;
            acc[1][0] += a.y*b.x; acc[1][1] += a.y*b.y; acc[1][2] += a.y*b.z; acc[1][3] += a.y*b.w;
            acc[2][0] += a.z*b.x; acc[2][1] += a.z*b.y; acc[2][2] += a.z*b.z; acc[2][3] += a.z*b.w;
            acc[3][0] += a.w*b.x; acc[3][1] += a.w*b.y; acc[3][2] += a.w*b.z; acc[3][3] += a.w*b.w;
        }
        __syncthreads();
    }

    #pragma unroll
    for (int i = 0; i < 4; i++) {
        int r = row0 + ty * 4 + i;
        float4 v = make_float4(acc[i][0], acc[i][1], acc[i][2], acc[i][3]);
        *(float4*)&out[(size_t)r * ND + col0 + tx * 4] = v;
    }
}

// ---------------------------------------------------------------------------
extern "C" void kernel_launch(void* const* d_in, const int* in_sizes, int n_in,
                              void* d_out, int out_size)
{
    const float* X  = (const float*)d_in[0];
    const float* Y  = (const float*)d_in[1];
    const float* Z  = (const float*)d_in[2];
    const float* Wq = (const float*)d_in[3];
    const float* Wk = (const float*)d_in[4];
    /* d_in[5] = Wv — intentionally unused (reference uses Wo for V) */
    const float* Wo = (const float*)d_in[6];
    float* out = (float*)d_out;

    proj_kernel<<<dim3(8, 128, 3), 256>>>(X, Y, Z, Wq, Wk, Wo);
    attn_kernel<<<dim3(32, 32), 256>>>();
    oproj_kernel<<<dim3(8, 128), 256>>>(Wo, out);
}

// round 8
// speedup vs baseline: 2.5471x; 2.5471x over previous
#include <cuda_runtime.h>
#include <cuda_bf16.h>
#include <cstdint>

#define NB  4
#define NS  2048
#define ND  512
#define NH  8
#define NHD 64
#define NROWS (NB*NS)   // 8192
#define KST 72          // padded bf16 row stride for [*][64] tiles (conflict-free frags)
#define VST 136         // padded bf16 row stride for [64][128] Vt tiles

typedef __nv_bfloat16 bf16;

// ---------------- device-global scratch (no allocations) --------------------
__device__ bf16 g_Ahi[3ull*NROWS*ND], g_Alo[3ull*NROWS*ND];   // X,Y,Z split
__device__ bf16 g_WThi[3ull*ND*ND],   g_WTlo[3ull*ND*ND];     // Wq^T,Wk^T,Wo^T split
__device__ bf16 g_Qhi[(size_t)NROWS*ND], g_Qlo[(size_t)NROWS*ND];  // [B,H,S,64]
__device__ bf16 g_Khi[(size_t)NROWS*ND], g_Klo[(size_t)NROWS*ND];
__device__ bf16 g_Vhi[(size_t)NROWS*ND], g_Vlo[(size_t)NROWS*ND];
__device__ bf16 g_Ohi[(size_t)NROWS*ND], g_Olo[(size_t)NROWS*ND];  // merged [B,S,D]

// ---------------- helpers ----------------------------------------------------
__device__ __forceinline__ void mma16816(float c[4], const uint32_t a[4], const uint32_t b[2]) {
    asm volatile("mma.sync.aligned.m16n8k16.row.col.f32.bf16.bf16.f32 "
        "{%0,%1,%2,%3}, {%4,%5,%6,%7}, {%8,%9}, {%0,%1,%2,%3};"
        : "+f"(c[0]), "+f"(c[1]), "+f"(c[2]), "+f"(c[3])
        : "r"(a[0]), "r"(a[1]), "r"(a[2]), "r"(a[3]), "r"(b[0]), "r"(b[1]));
}
__device__ __forceinline__ uint32_t packb(float x, float y) {
    __nv_bfloat162 h = __floats2bfloat162_rn(x, y);   // .x = low = x
    return *(uint32_t*)&h;
}
__device__ __forceinline__ uint32_t ldu32(const bf16* p) { return *(const uint32_t*)p; }

// ---------------- converts ---------------------------------------------------
// fp32 act [8192][512] -> bf16 hi/lo.  which = 0,1,2 (X,Y,Z)
__global__ __launch_bounds__(256) void convert_act(const float4* __restrict__ src, int which)
{
    size_t i = (size_t)blockIdx.x * 256 + threadIdx.x;
    bf16* hi = g_Ahi + (size_t)which*NROWS*ND;
    bf16* lo = g_Alo + (size_t)which*NROWS*ND;
    float4 v = src[i];
    float x[4] = {v.x, v.y, v.z, v.w};
    unsigned short h[4], l[4];
    #pragma unroll
    for (int j = 0; j < 4; j++) {
        bf16 hb = __float2bfloat16(x[j]);
        h[j] = __bfloat16_as_ushort(hb);
        l[j] = __bfloat16_as_ushort(__float2bfloat16(x[j] - __bfloat162float(hb)));
    }
    *(ushort4*)((unsigned short*)hi + 4*i) = make_ushort4(h[0],h[1],h[2],h[3]);
    *(ushort4*)((unsigned short*)lo + 4*i) = make_ushort4(l[0],l[1],l[2],l[3]);
}
// W[k][c] -> WT[c][k] hi/lo
__global__ __launch_bounds__(256) void convert_wt(const float* __restrict__ W, int mat)
{
    int k = blockIdx.x * 256 + threadIdx.x;
    int c = blockIdx.y;
    float x = W[(size_t)k * ND + c];
    bf16 hb = __float2bfloat16(x);
    g_WThi[(size_t)mat*ND*ND + (size_t)c*ND + k] = hb;
    g_WTlo[(size_t)mat*ND*ND + (size_t)c*ND + k] = __float2bfloat16(x - __bfloat162float(hb));
}

// ---------------- mma.sync GEMM: C[8192,512] = A @ W ------------------------
// Block tile 128x128, 8 warps (2m x 4n), warp tile 64x32, k-chunks of 64.
// mode 0: A = split acts (blockIdx.z picks X/Y/Z), out = bf16 hi/lo head-split Q/K/V
// mode 1: A = g_Ohi/g_Olo, W = Wo, out = fp32 (d_out)
#define GEMM_SMEM (4*128*KST*2)   // 73728 B
__global__ __launch_bounds__(256) void mma_gemm(float* __restrict__ outp, int mode)
{
    extern __shared__ bf16 sm[];
    bf16* Ah = sm;
    bf16* Al = sm + 128*KST;
    bf16* Bh = sm + 2*128*KST;
    bf16* Bl = sm + 3*128*KST;

    const int t = threadIdx.x, w = t >> 5, lane = t & 31;
    const int g = lane >> 2, tg = lane & 3;
    const int wm = w >> 2, wn = w & 3;
    const int row0 = blockIdx.y * 128, col0 = blockIdx.x * 128;
    const int mat = blockIdx.z;

    const bf16 *Agh, *Agl;
    if (mode == 0) { Agh = g_Ahi + (size_t)mat*NROWS*ND; Agl = g_Alo + (size_t)mat*NROWS*ND; }
    else           { Agh = g_Ohi; Agl = g_Olo; }
    const int wmat = (mode == 0) ? mat : 2;
    const bf16* Wh = g_WThi + (size_t)wmat*ND*ND;
    const bf16* Wl = g_WTlo + (size_t)wmat*ND*ND;

    float acc[4][4][4] = {};

    const int lr = t >> 1, lh = t & 1;    // loader: row, 32-col half
    for (int k0 = 0; k0 < ND; k0 += 64) {
        __syncthreads();
        const uint4* pAh = (const uint4*)(Agh + (size_t)(row0+lr)*ND + k0 + lh*32);
        const uint4* pAl = (const uint4*)(Agl + (size_t)(row0+lr)*ND + k0 + lh*32);
        const uint4* pBh = (const uint4*)(Wh  + (size_t)(col0+lr)*ND + k0 + lh*32);
        const uint4* pBl = (const uint4*)(Wl  + (size_t)(col0+lr)*ND + k0 + lh*32);
        uint4* sAh = (uint4*)(Ah + lr*KST + lh*32);
        uint4* sAl = (uint4*)(Al + lr*KST + lh*32);
        uint4* sBh = (uint4*)(Bh + lr*KST + lh*32);
        uint4* sBl = (uint4*)(Bl + lr*KST + lh*32);
        #pragma unroll
        for (int j = 0; j < 4; j++) {
            sAh[j] = pAh[j]; sAl[j] = pAl[j];
            sBh[j] = pBh[j]; sBl[j] = pBl[j];
        }
        __syncthreads();

        #pragma unroll
        for (int kf = 0; kf < 4; kf++) {
            uint32_t ah[4][4], al[4][4], bhv[4][2], blv[4][2];
            #pragma unroll
            for (int mf = 0; mf < 4; mf++) {
                const int r = wm*64 + mf*16 + g;
                const int kc = kf*16 + tg*2;
                ah[mf][0] = ldu32(&Ah[r*KST + kc]);
                ah[mf][1] = ldu32(&Ah[(r+8)*KST + kc]);
                ah[mf][2] = ldu32(&Ah[r*KST + kc + 8]);
                ah[mf][3] = ldu32(&Ah[(r+8)*KST + kc + 8]);
                al[mf][0] = ldu32(&Al[r*KST + kc]);
                al[mf][1] = ldu32(&Al[(r+8)*KST + kc]);
                al[mf][2] = ldu32(&Al[r*KST + kc + 8]);
                al[mf][3] = ldu32(&Al[(r+8)*KST + kc + 8]);
            }
            #pragma unroll
            for (int nf = 0; nf < 4; nf++) {
                const int c = wn*32 + nf*8 + g;
                const int kc = kf*16 + tg*2;
                bhv[nf][0] = ldu32(&Bh[c*KST + kc]);
                bhv[nf][1] = ldu32(&Bh[c*KST + kc + 8]);
                blv[nf][0] = ldu32(&Bl[c*KST + kc]);
                blv[nf][1] = ldu32(&Bl[c*KST + kc + 8]);
            }
            #pragma unroll
            for (int mf = 0; mf < 4; mf++)
                #pragma unroll
                for (int nf = 0; nf < 4; nf++) {
                    mma16816(acc[mf][nf], ah[mf], bhv[nf]);
                    mma16816(acc[mf][nf], ah[mf], blv[nf]);
                    mma16816(acc[mf][nf], al[mf], bhv[nf]);
                }
        }
    }

    // epilogue
    bf16 *OH = nullptr, *OL = nullptr;
    if (mode == 0) {
        if (mat == 0)      { OH = g_Qhi; OL = g_Qlo; }
        else if (mat == 1) { OH = g_Khi; OL = g_Klo; }
        else               { OH = g_Vhi; OL = g_Vlo; }
    }
    #pragma unroll
    for (int mf = 0; mf < 4; mf++)
        #pragma unroll
        for (int nf = 0; nf < 4; nf++) {
            const int cc = col0 + wn*32 + nf*8 + tg*2;
            #pragma unroll
            for (int rr = 0; rr < 2; rr++) {
                const int r = row0 + wm*64 + mf*16 + g + rr*8;
                float x0 = acc[mf][nf][rr*2], x1 = acc[mf][nf][rr*2+1];
                if (mode == 0) {
                    int b = r >> 11, s = r & 2047, h = cc >> 6, d = cc & 63;
                    size_t idx = (((size_t)(b*NH + h))*NS + s)*NHD + d;
                    float h0 = __bfloat162float(__float2bfloat16(x0));
                    float h1 = __bfloat162float(__float2bfloat16(x1));
                    *(uint32_t*)&OH[idx] = packb(x0, x1);
                    *(uint32_t*)&OL[idx] = packb(x0 - h0, x1 - h1);
                } else {
                    *(float2*)&outp[(size_t)r*ND + cc] = make_float2(x0, x1);
                }
            }
        }
}

// ---------------- attention: all-mma.sync flash kernel ----------------------
// grid (16, 32): 128 q-rows per CTA, (b,h) = blockIdx.y. 8 warps x 16 rows.
// Per 128-col k-tile: S = Q@K^T (bf16 split), ReLU->exp in regs, C-frag == A-frag
// layout reuse, P@V (split P, split V). Denominator accumulated per row.
#define ATTN_SMEM ((2*128*KST + 2*64*VST)*2)   // 71680 B
__global__ __launch_bounds__(256) void attn_kernel()
{
    extern __shared__ bf16 sm[];
    bf16* Kh  = sm;                 // [128][KST]  (also Q staging)
    bf16* Kl  = sm + 128*KST;
    bf16* Vth = sm + 2*128*KST;     // [64][VST]
    bf16* Vtl = Vth + 64*VST;

    const int t = threadIdx.x, w = t >> 5, lane = t & 31;
    const int g = lane >> 2, tg = lane & 3;
    const int bh = blockIdx.y, q0 = blockIdx.x * 128;
    const size_t base = (size_t)bh * NS * NHD;

    const int lr = t >> 1, lh = t & 1;

    // ---- stage Q through smem, extract per-warp A-frags (held in regs all loop)
    {
        const uint4* ph = (const uint4*)(g_Qhi + base + (size_t)(q0+lr)*NHD + lh*32);
        const uint4* pl = (const uint4*)(g_Qlo + base + (size_t)(q0+lr)*NHD + lh*32);
        uint4* sh = (uint4*)(Kh + lr*KST + lh*32);
        uint4* sl = (uint4*)(Kl + lr*KST + lh*32);
        #pragma unroll
        for (int j = 0; j < 4; j++) { sh[j] = ph[j]; sl[j] = pl[j]; }
    }
    __syncthreads();
    uint32_t qh[4][4], ql[4][4];
    {
        const int r = w*16 + g;
        #pragma unroll
        for (int kf = 0; kf < 4; kf++) {
            const int kc = kf*16 + tg*2;
            qh[kf][0] = ldu32(&Kh[r*KST + kc]);
            qh[kf][1] = ldu32(&Kh[(r+8)*KST + kc]);
            qh[kf][2] = ldu32(&Kh[r*KST + kc + 8]);
            qh[kf][3] = ldu32(&Kh[(r+8)*KST + kc + 8]);
            ql[kf][0] = ldu32(&Kl[r*KST + kc]);
            ql[kf][1] = ldu32(&Kl[(r+8)*KST + kc]);
            ql[kf][2] = ldu32(&Kl[r*KST + kc + 8]);
            ql[kf][3] = ldu32(&Kl[(r+8)*KST + kc + 8]);
        }
    }

    float oacc[8][4] = {};
    float lsum[2] = {0.f, 0.f};

    for (int j0 = 0; j0 < NS; j0 += 128) {
        __syncthreads();   // previous tile fully consumed
        // load K row-major; V transposed into Vt[d][kcol]
        {
            const uint4* pkh = (const uint4*)(g_Khi + base + (size_t)(j0+lr)*NHD + lh*32);
            const uint4* pkl = (const uint4*)(g_Klo + base + (size_t)(j0+lr)*NHD + lh*32);
            uint4* skh = (uint4*)(Kh + lr*KST + lh*32);
            uint4* skl = (uint4*)(Kl + lr*KST + lh*32);
            const uint4* pvh = (const uint4*)(g_Vhi + base + (size_t)(j0+lr)*NHD + lh*32);
            const uint4* pvl = (const uint4*)(g_Vlo + base + (size_t)(j0+lr)*NHD + lh*32);
            #pragma unroll
            for (int j = 0; j < 4; j++) {
                skh[j] = pkh[j]; skl[j] = pkl[j];
                uint4 vh = pvh[j], vl = pvl[j];
                bf16 th[8], tl[8];
                *(uint4*)th = vh; *(uint4*)tl = vl;
                const int d0 = lh*32 + j*8;
                #pragma unroll
                for (int e = 0; e < 8; e++) {
                    Vth[(d0+e)*VST + lr] = th[e];
                    Vtl[(d0+e)*VST + lr] = tl[e];
                }
            }
        }
        __syncthreads();

        #pragma unroll
        for (int hn = 0; hn < 2; hn++) {        // two 64-col halves of S
            float c[8][4] = {};
            #pragma unroll
            for (int kf = 0; kf < 4; kf++) {
                #pragma unroll
                for (int nf = 0; nf < 8; nf++) {
                    const int n = hn*64 + nf*8 + g;
                    const int kc = kf*16 + tg*2;
                    uint32_t bh0[2] = { ldu32(&Kh[n*KST + kc]), ldu32(&Kh[n*KST + kc + 8]) };
                    uint32_t bl0[2] = { ldu32(&Kl[n*KST + kc]), ldu32(&Kl[n*KST + kc + 8]) };
                    mma16816(c[nf], qh[kf], bh0);
                    mma16816(c[nf], qh[kf], bl0);
                    mma16816(c[nf], ql[kf], bh0);
                }
            }
            // scale + ReLU + exp; accumulate row denominators
            #pragma unroll
            for (int nf = 0; nf < 8; nf++)
                #pragma unroll
                for (int i = 0; i < 4; i++) {
                    float p = __expf(fmaxf(c[nf][i]*0.125f, 0.f));
                    c[nf][i] = p;
                    lsum[i>>1] += p;
                }
            // pack P into A-frags (C layout == A layout, zero shuffles), hi/lo split
            uint32_t ph[4][4], pl[4][4];
            #pragma unroll
            for (int kq = 0; kq < 4; kq++) {
                #pragma unroll
                for (int half = 0; half < 2; half++) {   // n-frag 2kq+half -> a regs 2half,2half+1
                    const float* cv = c[2*kq + half];
                    float h0 = __bfloat162float(__float2bfloat16(cv[0]));
                    float h1 = __bfloat162float(__float2bfloat16(cv[1]));
                    float h2 = __bfloat162float(__float2bfloat16(cv[2]));
                    float h3 = __bfloat162float(__float2bfloat16(cv[3]));
                    ph[kq][2*half+0] = packb(cv[0], cv[1]);
                    ph[kq][2*half+1] = packb(cv[2], cv[3]);
                    pl[kq][2*half+0] = packb(cv[0]-h0, cv[1]-h1);
                    pl[kq][2*half+1] = packb(cv[2]-h2, cv[3]-h3);
                }
            }
            // O += P @ V
            #pragma unroll
            for (int kq = 0; kq < 4; kq++) {
                const int kc = hn*64 + kq*16 + tg*2;
                #pragma unroll
                for (int nf = 0; nf < 8; nf++) {
                    const int n = nf*8 + g;
                    uint32_t bv[2]  = { ldu32(&Vth[n*VST + kc]), ldu32(&Vth[n*VST + kc + 8]) };
                    uint32_t bvl[2] = { ldu32(&Vtl[n*VST + kc]), ldu32(&Vtl[n*VST + kc + 8]) };
                    mma16816(oacc[nf], ph[kq], bv);
                    mma16816(oacc[nf], pl[kq], bv);
                    mma16816(oacc[nf], ph[kq], bvl);
                }
            }
        }
    }

    // reduce denominators across the 4 lanes sharing each row
    #pragma unroll
    for (int i = 0; i < 2; i++) {
        lsum[i] += __shfl_xor_sync(0xffffffffu, lsum[i], 1);
        lsum[i] += __shfl_xor_sync(0xffffffffu, lsum[i], 2);
    }
    const float inv0 = 1.f / lsum[0], inv1 = 1.f / lsum[1];

    const int b = bh >> 3, h = bh & 7;
    #pragma unroll
    for (int nf = 0; nf < 8; nf++) {
        const int col = h*NHD + nf*8 + tg*2;
        #pragma unroll
        for (int rr = 0; rr < 2; rr++) {
            const int srow = q0 + w*16 + g + rr*8;
            const float inv = rr ? inv1 : inv0;
            float x0 = oacc[nf][rr*2]*inv, x1 = oacc[nf][rr*2+1]*inv;
            float h0 = __bfloat162float(__float2bfloat16(x0));
            float h1 = __bfloat162float(__float2bfloat16(x1));
            size_t idx = ((size_t)(b*NS + srow))*ND + col;
            *(uint32_t*)&g_Ohi[idx] = packb(x0, x1);
            *(uint32_t*)&g_Olo[idx] = packb(x0 - h0, x1 - h1);
        }
    }
}

// ---------------------------------------------------------------------------
extern "C" void kernel_launch(void* const* d_in, const int* in_sizes, int n_in,
                              void* d_out, int out_size)
{
    const float* X  = (const float*)d_in[0];
    const float* Y  = (const float*)d_in[1];
    const float* Z  = (const float*)d_in[2];
    const float* Wq = (const float*)d_in[3];
    const float* Wk = (const float*)d_in[4];
    /* d_in[5] = Wv unused (reference uses Wo for V projection) */
    const float* Wo = (const float*)d_in[6];
    float* out = (float*)d_out;

    static bool attr_done = false;
    if (!attr_done) {
        cudaFuncSetAttribute(mma_gemm,   cudaFuncAttributeMaxDynamicSharedMemorySize, GEMM_SMEM);
        cudaFuncSetAttribute(attn_kernel, cudaFuncAttributeMaxDynamicSharedMemorySize, ATTN_SMEM);
        attr_done = true;
    }

    convert_wt<<<dim3(2, 512), 256>>>(Wq, 0);
    convert_wt<<<dim3(2, 512), 256>>>(Wk, 1);
    convert_wt<<<dim3(2, 512), 256>>>(Wo, 2);
    convert_act<<<NROWS*ND/4/256, 256>>>((const float4*)X, 0);
    convert_act<<<NROWS*ND/4/256, 256>>>((const float4*)Y, 1);
    convert_act<<<NROWS*ND/4/256, 256>>>((const float4*)Z, 2);

    mma_gemm<<<dim3(4, 64, 3), 256, GEMM_SMEM>>>(nullptr, 0);   // Q,K,V projections
    attn_kernel<<<dim3(16, 32), 256, ATTN_SMEM>>>();            // fused attention
    mma_gemm<<<dim3(4, 64, 1), 256, GEMM_SMEM>>>(out, 1);       // O @ Wo
}

// round 9
// speedup vs baseline: 2.7004x; 1.0602x over previous
#include <cuda_runtime.h>
#include <cuda_bf16.h>
#include <cstdint>

#define NB  4
#define NS  2048
#define ND  512
#define NH  8
#define NHD 64
#define NROWS (NB*NS)   // 8192
#define KST 72          // padded bf16 row stride (144B): ldmatrix conflict-free

typedef __nv_bfloat16 bf16;

// ---------------- device-global scratch -------------------------------------
__device__ bf16 g_Ahi[3ull*NROWS*ND], g_Alo[3ull*NROWS*ND];
__device__ bf16 g_WThi[3ull*ND*ND],   g_WTlo[3ull*ND*ND];
__device__ bf16 g_Qhi[(size_t)NROWS*ND], g_Qlo[(size_t)NROWS*ND];  // [B,H,S,64]
__device__ bf16 g_Khi[(size_t)NROWS*ND], g_Klo[(size_t)NROWS*ND];
__device__ bf16 g_Vhi[(size_t)NROWS*ND], g_Vlo[(size_t)NROWS*ND];
__device__ bf16 g_Ohi[(size_t)NROWS*ND], g_Olo[(size_t)NROWS*ND];

// ---------------- helpers ----------------------------------------------------
__device__ __forceinline__ void mma16816(float c[4], const uint32_t a[4], const uint32_t b[2]) {
    asm volatile("mma.sync.aligned.m16n8k16.row.col.f32.bf16.bf16.f32 "
        "{%0,%1,%2,%3}, {%4,%5,%6,%7}, {%8,%9}, {%0,%1,%2,%3};"
        : "+f"(c[0]), "+f"(c[1]), "+f"(c[2]), "+f"(c[3])
        : "r"(a[0]), "r"(a[1]), "r"(a[2]), "r"(a[3]), "r"(b[0]), "r"(b[1]));
}
__device__ __forceinline__ uint32_t packb(float x, float y) {
    __nv_bfloat162 h = __floats2bfloat162_rn(x, y);
    return *(uint32_t*)&h;
}
__device__ __forceinline__ uint32_t smem_u32(const void* p) {
    uint32_t a;
    asm("{ .reg .u64 t; cvta.to.shared.u64 t, %1; cvt.u32.u64 %0, t; }" : "=r"(a) : "l"(p));
    return a;
}
__device__ __forceinline__ void ldsm4(uint32_t r[4], uint32_t addr) {
    asm volatile("ldmatrix.sync.aligned.m8n8.x4.shared.b16 {%0,%1,%2,%3}, [%4];"
        : "=r"(r[0]), "=r"(r[1]), "=r"(r[2]), "=r"(r[3]) : "r"(addr));
}
__device__ __forceinline__ void ldsm4t(uint32_t r[4], uint32_t addr) {
    asm volatile("ldmatrix.sync.aligned.m8n8.x4.trans.shared.b16 {%0,%1,%2,%3}, [%4];"
        : "=r"(r[0]), "=r"(r[1]), "=r"(r[2]), "=r"(r[3]) : "r"(addr));
}
#define CPA(sd, gs) \
    asm volatile("cp.async.cg.shared.global [%0], [%1], 16;" :: "r"(sd), "l"(gs) : "memory")
#define CPCOMMIT() asm volatile("cp.async.commit_group;" ::: "memory")
#define CPWAIT(n)  asm volatile("cp.async.wait_group %0;" :: "n"(n) : "memory")

// ---------------- converts ---------------------------------------------------
__global__ __launch_bounds__(256) void convert_act(const float4* __restrict__ src, int which)
{
    size_t i = (size_t)blockIdx.x * 256 + threadIdx.x;
    bf16* hi = g_Ahi + (size_t)which*NROWS*ND;
    bf16* lo = g_Alo + (size_t)which*NROWS*ND;
    float4 v = src[i];
    float x[4] = {v.x, v.y, v.z, v.w};
    unsigned short h[4], l[4];
    #pragma unroll
    for (int j = 0; j < 4; j++) {
        bf16 hb = __float2bfloat16(x[j]);
        h[j] = __bfloat16_as_ushort(hb);
        l[j] = __bfloat16_as_ushort(__float2bfloat16(x[j] - __bfloat162float(hb)));
    }
    *(ushort4*)((unsigned short*)hi + 4*i) = make_ushort4(h[0],h[1],h[2],h[3]);
    *(ushort4*)((unsigned short*)lo + 4*i) = make_ushort4(l[0],l[1],l[2],l[3]);
}
// coalesced W -> WT transpose + split, all 3 mats in one launch
__global__ __launch_bounds__(256) void convert_wt(
    const float* __restrict__ Wq, const float* __restrict__ Wk, const float* __restrict__ Wo)
{
    __shared__ float tile[32][33];
    const int z = blockIdx.z;
    const float* W = (z == 0) ? Wq : (z == 1) ? Wk : Wo;
    const int tx = threadIdx.x & 31, ty = threadIdx.x >> 5;   // 32 x 8
    const int x0 = blockIdx.x * 32, y0 = blockIdx.y * 32;
    #pragma unroll
    for (int i = ty; i < 32; i += 8)
        tile[i][tx] = W[(size_t)(y0 + i) * ND + x0 + tx];
    __syncthreads();
    bf16* hi = g_WThi + (size_t)z*ND*ND;
    bf16* lo = g_WTlo + (size_t)z*ND*ND;
    #pragma unroll
    for (int i = ty; i < 32; i += 8) {
        float x = tile[tx][i];                     // = W[y0+tx][x0+i]
        bf16 hb = __float2bfloat16(x);
        hi[(size_t)(x0 + i) * ND + y0 + tx] = hb;
        lo[(size_t)(x0 + i) * ND + y0 + tx] = __float2bfloat16(x - __bfloat162float(hb));
    }
}

// ---------------- mma.sync GEMM: C[8192,512] = A @ W ------------------------
// 128x128 block tile, 8 warps (2m x 4n), k-chunks of 64, cp.async 2-stage.
#define GEMM_SMEM (2*4*128*KST*2)   // 147456
__global__ __launch_bounds__(256) void mma_gemm(float* __restrict__ outp, int mode)
{
    extern __shared__ bf16 sm[];
    const int t = threadIdx.x, w = t >> 5, lane = t & 31;
    const int g = lane >> 2, tg = lane & 3;
    const int G = lane >> 3, rr = lane & 7;
    const int wm = w >> 2, wn = w & 3;
    const int row0 = blockIdx.y * 128, col0 = blockIdx.x * 128;
    const int mat = blockIdx.z;
    const int lr = t >> 1, lh = t & 1;

    const bf16 *Agh, *Agl;
    if (mode == 0) { Agh = g_Ahi + (size_t)mat*NROWS*ND; Agl = g_Alo + (size_t)mat*NROWS*ND; }
    else           { Agh = g_Ohi; Agl = g_Olo; }
    const int wmat = (mode == 0) ? mat : 2;
    const bf16* Wh = g_WThi + (size_t)wmat*ND*ND;
    const bf16* Wl = g_WTlo + (size_t)wmat*ND*ND;

    const uint32_t smb = smem_u32(sm);
#define GARR(s, a) (smb + (uint32_t)(((s)*4 + (a)) * 128 * KST * 2))

#define GEMM_LOAD(k0, s) do {                                                   \
    const bf16* _g0 = Agh + (size_t)(row0+lr)*ND + (k0) + lh*32;                \
    const bf16* _g1 = Agl + (size_t)(row0+lr)*ND + (k0) + lh*32;                \
    const bf16* _g2 = Wh  + (size_t)(col0+lr)*ND + (k0) + lh*32;                \
    const bf16* _g3 = Wl  + (size_t)(col0+lr)*ND + (k0) + lh*32;                \
    uint32_t _sd = (uint32_t)(lr*KST + lh*32)*2;                                \
    _Pragma("unroll") for (int v = 0; v < 4; v++) {                             \
        CPA(GARR(s,0) + _sd + v*16, _g0 + v*8);                                 \
        CPA(GARR(s,1) + _sd + v*16, _g1 + v*8);                                 \
        CPA(GARR(s,2) + _sd + v*16, _g2 + v*8);                                 \
        CPA(GARR(s,3) + _sd + v*16, _g3 + v*8);                                 \
    } } while (0)

    float acc[4][4][4] = {};

    GEMM_LOAD(0, 0); CPCOMMIT();

    for (int c = 0; c < 8; c++) {
        const int s = c & 1;
        __syncthreads();                       // buffer s^1 free (consumed in c-1)
        if (c < 7) { GEMM_LOAD((c+1)*64, s^1); CPCOMMIT(); CPWAIT(1); }
        else       { CPWAIT(0); }
        __syncthreads();                       // chunk c visible to all

        #pragma unroll
        for (int kf = 0; kf < 4; kf++) {
            uint32_t ah[4][4], al[4][4];
            #pragma unroll
            for (int mf = 0; mf < 4; mf++) {
                uint32_t r = wm*64 + mf*16 + (G & 1)*8 + rr;
                uint32_t cc = kf*16 + (G >> 1)*8;
                ldsm4(ah[mf], GARR(s,0) + (r*KST + cc)*2);
                ldsm4(al[mf], GARR(s,1) + (r*KST + cc)*2);
            }
            uint32_t bhv[2][4], blv[2][4];
            #pragma unroll
            for (int n2 = 0; n2 < 2; n2++) {
                uint32_t r = wn*32 + n2*16 + (G >> 1)*8 + rr;
                uint32_t cc = kf*16 + (G & 1)*8;
                ldsm4(bhv[n2], GARR(s,2) + (r*KST + cc)*2);
                ldsm4(blv[n2], GARR(s,3) + (r*KST + cc)*2);
            }
            #pragma unroll
            for (int mf = 0; mf < 4; mf++)
                #pragma unroll
                for (int nf = 0; nf < 4; nf++) {
                    const uint32_t* bh2 = &bhv[nf>>1][(nf&1)*2];
                    const uint32_t* bl2 = &blv[nf>>1][(nf&1)*2];
                    mma16816(acc[mf][nf], ah[mf], bh2);
                    mma16816(acc[mf][nf], ah[mf], bl2);
                    mma16816(acc[mf][nf], al[mf], bh2);
                }
        }
    }

    bf16 *OH = nullptr, *OL = nullptr;
    if (mode == 0) {
        if (mat == 0)      { OH = g_Qhi; OL = g_Qlo; }
        else if (mat == 1) { OH = g_Khi; OL = g_Klo; }
        else               { OH = g_Vhi; OL = g_Vlo; }
    }
    #pragma unroll
    for (int mf = 0; mf < 4; mf++)
        #pragma unroll
        for (int nf = 0; nf < 4; nf++) {
            const int cc = col0 + wn*32 + nf*8 + tg*2;
            #pragma unroll
            for (int rr2 = 0; rr2 < 2; rr2++) {
                const int r = row0 + wm*64 + mf*16 + g + rr2*8;
                float x0 = acc[mf][nf][rr2*2], x1 = acc[mf][nf][rr2*2+1];
                if (mode == 0) {
                    int b = r >> 11, sN = r & 2047, h = cc >> 6, d = cc & 63;
                    size_t idx = (((size_t)(b*NH + h))*NS + sN)*NHD + d;
                    float h0 = __bfloat162float(__float2bfloat16(x0));
                    float h1 = __bfloat162float(__float2bfloat16(x1));
                    *(uint32_t*)&OH[idx] = packb(x0, x1);
                    *(uint32_t*)&OL[idx] = packb(x0 - h0, x1 - h1);
                } else {
                    *(float2*)&outp[(size_t)r*ND + cc] = make_float2(x0, x1);
                }
            }
        }
}

// ---------------- attention: mma.sync + ldmatrix + cp.async pipeline --------
// grid (16, 32): 128 q-rows per CTA. V kept row-major; ldmatrix.trans gives
// PV B-frags directly. 2-stage cp.async pipeline over 128-row k-tiles.
#define ATTN_SMEM (2*4*128*KST*2)   // 147456
__global__ __launch_bounds__(256) void attn_kernel()
{
    extern __shared__ bf16 sm[];
    const int t = threadIdx.x, w = t >> 5, lane = t & 31;
    const int g = lane >> 2, tg = lane & 3;
    const int G = lane >> 3, rr = lane & 7;
    const int bh = blockIdx.y, q0 = blockIdx.x * 128;
    const size_t base = (size_t)bh * NS * NHD;
    const int lr = t >> 1, lh = t & 1;

    const uint32_t smb = smem_u32(sm);
#define AARR(s, a) (smb + (uint32_t)(((s)*4 + (a)) * 128 * KST * 2))

#define ATTN_LOAD(j0, s) do {                                                   \
    const bf16* _g0 = g_Khi + base + (size_t)((j0)+lr)*NHD + lh*32;             \
    const bf16* _g1 = g_Klo + base + (size_t)((j0)+lr)*NHD + lh*32;             \
    const bf16* _g2 = g_Vhi + base + (size_t)((j0)+lr)*NHD + lh*32;             \
    const bf16* _g3 = g_Vlo + base + (size_t)((j0)+lr)*NHD + lh*32;             \
    uint32_t _sd = (uint32_t)(lr*KST + lh*32)*2;                                \
    _Pragma("unroll") for (int v = 0; v < 4; v++) {                             \
        CPA(AARR(s,0) + _sd + v*16, _g0 + v*8);                                 \
        CPA(AARR(s,1) + _sd + v*16, _g1 + v*8);                                 \
        CPA(AARR(s,2) + _sd + v*16, _g2 + v*8);                                 \
        CPA(AARR(s,3) + _sd + v*16, _g3 + v*8);                                 \
    } } while (0)

    // prologue: tile0 -> stage0 ; Q -> stage1 arrays 0/1
    ATTN_LOAD(0, 0); CPCOMMIT();
    {
        const bf16* q_h = g_Qhi + base + (size_t)(q0+lr)*NHD + lh*32;
        const bf16* q_l = g_Qlo + base + (size_t)(q0+lr)*NHD + lh*32;
        uint32_t sd = (uint32_t)(lr*KST + lh*32)*2;
        #pragma unroll
        for (int v = 0; v < 4; v++) {
            CPA(AARR(1,0) + sd + v*16, q_h + v*8);
            CPA(AARR(1,1) + sd + v*16, q_l + v*8);
        }
        CPCOMMIT();
    }
    CPWAIT(0);
    __syncthreads();

    // extract Q a-frags (held in regs for the whole loop)
    uint32_t qh[4][4], ql[4][4];
    #pragma unroll
    for (int kf = 0; kf < 4; kf++) {
        uint32_t r = w*16 + (G & 1)*8 + rr;
        uint32_t cc = kf*16 + (G >> 1)*8;
        ldsm4(qh[kf], AARR(1,0) + (r*KST + cc)*2);
        ldsm4(ql[kf], AARR(1,1) + (r*KST + cc)*2);
    }

    float oacc[8][4] = {};
    float lsum[2] = {0.f, 0.f};

    for (int j = 0; j < 16; j++) {
        const int s = j & 1;
        __syncthreads();   // stage s^1 free (Q frags extracted / tile j-1 consumed)
        if (j < 15) { ATTN_LOAD((j+1)*128, s^1); CPCOMMIT(); CPWAIT(1); }
        else        { CPWAIT(0); }
        __syncthreads();   // tile j visible

        #pragma unroll
        for (int hn = 0; hn < 2; hn++) {
            float c[8][4] = {};
            #pragma unroll
            for (int kf = 0; kf < 4; kf++) {
                #pragma unroll
                for (int n2 = 0; n2 < 4; n2++) {
                    uint32_t brow = hn*64 + n2*16 + (G >> 1)*8 + rr;
                    uint32_t bcol = kf*16 + (G & 1)*8;
                    uint32_t kb[4], klb[4];
                    ldsm4(kb,  AARR(s,0) + (brow*KST + bcol)*2);
                    ldsm4(klb, AARR(s,1) + (brow*KST + bcol)*2);
                    mma16816(c[n2*2],   qh[kf], &kb[0]);
                    mma16816(c[n2*2],   qh[kf], &klb[0]);
                    mma16816(c[n2*2],   ql[kf], &kb[0]);
                    mma16816(c[n2*2+1], qh[kf], &kb[2]);
                    mma16816(c[n2*2+1], qh[kf], &klb[2]);
                    mma16816(c[n2*2+1], ql[kf], &kb[2]);
                }
            }
            // scale + ReLU + exp, accumulate denominators
            #pragma unroll
            for (int nf = 0; nf < 8; nf++)
                #pragma unroll
                for (int i = 0; i < 4; i++) {
                    float p = __expf(fmaxf(c[nf][i]*0.125f, 0.f));
                    c[nf][i] = p;
                    lsum[i>>1] += p;
                }
            // pack P: C-frag layout == A-frag layout (zero shuffles)
            uint32_t ph[4][4], pl[4][4];
            #pragma unroll
            for (int kq = 0; kq < 4; kq++)
                #pragma unroll
                for (int half = 0; half < 2; half++) {
                    const float* cv = c[2*kq + half];
                    float h0 = __bfloat162float(__float2bfloat16(cv[0]));
                    float h1 = __bfloat162float(__float2bfloat16(cv[1]));
                    float h2 = __bfloat162float(__float2bfloat16(cv[2]));
                    float h3 = __bfloat162float(__float2bfloat16(cv[3]));
                    ph[kq][2*half+0] = packb(cv[0], cv[1]);
                    ph[kq][2*half+1] = packb(cv[2], cv[3]);
                    pl[kq][2*half+0] = packb(cv[0]-h0, cv[1]-h1);
                    pl[kq][2*half+1] = packb(cv[2]-h2, cv[3]-h3);
                }
            // O += P @ V   (V row-major, ldmatrix.trans -> B-frags)
            #pragma unroll
            for (int kq = 0; kq < 4; kq++) {
                const uint32_t kc0 = hn*64 + kq*16;
                #pragma unroll
                for (int d2 = 0; d2 < 4; d2++) {
                    uint32_t vrow = kc0 + (G & 1)*8 + rr;
                    uint32_t vcol = d2*16 + (G >> 1)*8;
                    uint32_t vb[4], vlb[4];
                    ldsm4t(vb,  AARR(s,2) + (vrow*KST + vcol)*2);
                    ldsm4t(vlb, AARR(s,3) + (vrow*KST + vcol)*2);
                    mma16816(oacc[d2*2],   ph[kq], &vb[0]);
                    mma16816(oacc[d2*2],   pl[kq], &vb[0]);
                    mma16816(oacc[d2*2],   ph[kq], &vlb[0]);
                    mma16816(oacc[d2*2+1], ph[kq], &vb[2]);
                    mma16816(oacc[d2*2+1], pl[kq], &vb[2]);
                    mma16816(oacc[d2*2+1], ph[kq], &vlb[2]);
                }
            }
        }
    }

    #pragma unroll
    for (int i = 0; i < 2; i++) {
        lsum[i] += __shfl_xor_sync(0xffffffffu, lsum[i], 1);
        lsum[i] += __shfl_xor_sync(0xffffffffu, lsum[i], 2);
    }
    const float inv0 = 1.f / lsum[0], inv1 = 1.f / lsum[1];

    const int b = bh >> 3, h = bh & 7;
    #pragma unroll
    for (int nf = 0; nf < 8; nf++) {
        const int col = h*NHD + nf*8 + tg*2;
        #pragma unroll
        for (int rr2 = 0; rr2 < 2; rr2++) {
            const int srow = q0 + w*16 + g + rr2*8;
            const float inv = rr2 ? inv1 : inv0;
            float x0 = oacc[nf][rr2*2]*inv, x1 = oacc[nf][rr2*2+1]*inv;
            float h0 = __bfloat162float(__float2bfloat16(x0));
            float h1 = __bfloat162float(__float2bfloat16(x1));
            size_t idx = ((size_t)(b*NS + srow))*ND + col;
            *(uint32_t*)&g_Ohi[idx] = packb(x0, x1);
            *(uint32_t*)&g_Olo[idx] = packb(x0 - h0, x1 - h1);
        }
    }
}

// ---------------------------------------------------------------------------
extern "C" void kernel_launch(void* const* d_in, const int* in_sizes, int n_in,
                              void* d_out, int out_size)
{
    const float* X  = (const float*)d_in[0];
    const float* Y  = (const float*)d_in[1];
    const float* Z  = (const float*)d_in[2];
    const float* Wq = (const float*)d_in[3];
    const float* Wk = (const float*)d_in[4];
    /* d_in[5] = Wv unused (reference uses Wo for V projection) */
    const float* Wo = (const float*)d_in[6];
    float* out = (float*)d_out;

    static bool attr_done = false;
    if (!attr_done) {
        cudaFuncSetAttribute(mma_gemm,    cudaFuncAttributeMaxDynamicSharedMemorySize, GEMM_SMEM);
        cudaFuncSetAttribute(attn_kernel, cudaFuncAttributeMaxDynamicSharedMemorySize, ATTN_SMEM);
        attr_done = true;
    }

    // launch order puts attn_kernel at index 5 so ncu (-s 5 -c 1) captures it
    convert_wt<<<dim3(16, 16, 3), 256>>>(Wq, Wk, Wo);             // 0
    convert_act<<<NROWS*ND/4/256, 256>>>((const float4*)X, 0);    // 1
    convert_act<<<NROWS*ND/4/256, 256>>>((const float4*)Y, 1);    // 2
    convert_act<<<NROWS*ND/4/256, 256>>>((const float4*)Z, 2);    // 3
    mma_gemm<<<dim3(4, 64, 3), 256, GEMM_SMEM>>>(nullptr, 0);     // 4
    attn_kernel<<<dim3(16, 32), 256, ATTN_SMEM>>>();              // 5  <- profiled
    mma_gemm<<<dim3(4, 64, 1), 256, GEMM_SMEM>>>(out, 1);         // 6
}

// round 10
// speedup vs baseline: 3.1576x; 1.1693x over previous
#include <cuda_runtime.h>
#include <cuda_bf16.h>
#include <cstdint>

#define NB  4
#define NS  2048
#define ND  512
#define NH  8
#define NHD 64
#define NROWS (NB*NS)   // 8192
#define KSTA 72         // attn smem row stride (144B) — ldmatrix conflict-free
#define KSTG 40         // gemm smem row stride (80B)  — ldmatrix conflict-free

typedef __nv_bfloat16 bf16;

// ---------------- device-global scratch -------------------------------------
__device__ bf16 g_Ahi[3ull*NROWS*ND], g_Alo[3ull*NROWS*ND];
__device__ bf16 g_WThi[3ull*ND*ND],   g_WTlo[3ull*ND*ND];
__device__ bf16 g_Qhi[(size_t)NROWS*ND], g_Qlo[(size_t)NROWS*ND];  // [B,H,S,64]
__device__ bf16 g_Khi[(size_t)NROWS*ND], g_Klo[(size_t)NROWS*ND];
__device__ bf16 g_Vhi[(size_t)NROWS*ND], g_Vlo[(size_t)NROWS*ND];
__device__ bf16 g_Ohi[(size_t)NROWS*ND], g_Olo[(size_t)NROWS*ND];

// ---------------- helpers ----------------------------------------------------
__device__ __forceinline__ void mma16816(float c[4], const uint32_t a[4], const uint32_t b[2]) {
    asm volatile("mma.sync.aligned.m16n8k16.row.col.f32.bf16.bf16.f32 "
        "{%0,%1,%2,%3}, {%4,%5,%6,%7}, {%8,%9}, {%0,%1,%2,%3};"
        : "+f"(c[0]), "+f"(c[1]), "+f"(c[2]), "+f"(c[3])
        : "r"(a[0]), "r"(a[1]), "r"(a[2]), "r"(a[3]), "r"(b[0]), "r"(b[1]));
}
__device__ __forceinline__ uint32_t packb(float x, float y) {
    __nv_bfloat162 h = __floats2bfloat162_rn(x, y);
    return *(uint32_t*)&h;
}
__device__ __forceinline__ uint32_t smem_u32(const void* p) {
    uint32_t a;
    asm("{ .reg .u64 t; cvta.to.shared.u64 t, %1; cvt.u32.u64 %0, t; }" : "=r"(a) : "l"(p));
    return a;
}
__device__ __forceinline__ void ldsm4(uint32_t r[4], uint32_t addr) {
    asm volatile("ldmatrix.sync.aligned.m8n8.x4.shared.b16 {%0,%1,%2,%3}, [%4];"
        : "=r"(r[0]), "=r"(r[1]), "=r"(r[2]), "=r"(r[3]) : "r"(addr));
}
__device__ __forceinline__ void ldsm4t(uint32_t r[4], uint32_t addr) {
    asm volatile("ldmatrix.sync.aligned.m8n8.x4.trans.shared.b16 {%0,%1,%2,%3}, [%4];"
        : "=r"(r[0]), "=r"(r[1]), "=r"(r[2]), "=r"(r[3]) : "r"(addr));
}
#define CPA(sd, gs) \
    asm volatile("cp.async.cg.shared.global [%0], [%1], 16;" :: "r"(sd), "l"(gs) : "memory")
#define CPCOMMIT() asm volatile("cp.async.commit_group;" ::: "memory")
#define CPWAIT(n)  asm volatile("cp.async.wait_group %0;" :: "n"(n) : "memory")

// ---------------- converts ---------------------------------------------------
__global__ __launch_bounds__(256) void convert_act(const float4* __restrict__ src, int which)
{
    size_t i = (size_t)blockIdx.x * 256 + threadIdx.x;
    bf16* hi = g_Ahi + (size_t)which*NROWS*ND;
    bf16* lo = g_Alo + (size_t)which*NROWS*ND;
    float4 v = src[i];
    float x[4] = {v.x, v.y, v.z, v.w};
    unsigned short h[4], l[4];
    #pragma unroll
    for (int j = 0; j < 4; j++) {
        bf16 hb = __float2bfloat16(x[j]);
        h[j] = __bfloat16_as_ushort(hb);
        l[j] = __bfloat16_as_ushort(__float2bfloat16(x[j] - __bfloat162float(hb)));
    }
    *(ushort4*)((unsigned short*)hi + 4*i) = make_ushort4(h[0],h[1],h[2],h[3]);
    *(ushort4*)((unsigned short*)lo + 4*i) = make_ushort4(l[0],l[1],l[2],l[3]);
}
__global__ __launch_bounds__(256) void convert_wt(
    const float* __restrict__ Wq, const float* __restrict__ Wk, const float* __restrict__ Wo)
{
    __shared__ float tile[32][33];
    const int z = blockIdx.z;
    const float* W = (z == 0) ? Wq : (z == 1) ? Wk : Wo;
    const int tx = threadIdx.x & 31, ty = threadIdx.x >> 5;
    const int x0 = blockIdx.x * 32, y0 = blockIdx.y * 32;
    #pragma unroll
    for (int i = ty; i < 32; i += 8)
        tile[i][tx] = W[(size_t)(y0 + i) * ND + x0 + tx];
    __syncthreads();
    bf16* hi = g_WThi + (size_t)z*ND*ND;
    bf16* lo = g_WTlo + (size_t)z*ND*ND;
    #pragma unroll
    for (int i = ty; i < 32; i += 8) {
        float x = tile[tx][i];
        bf16 hb = __float2bfloat16(x);
        hi[(size_t)(x0 + i) * ND + y0 + tx] = hb;
        lo[(size_t)(x0 + i) * ND + y0 + tx] = __float2bfloat16(x - __bfloat162float(hb));
    }
}

// ---------------- mma.sync GEMM: C[8192,512] = A @ W ------------------------
// 128x128 block tile, 8 warps (2m x 4n), k-chunks of 32, 2-stage cp.async.
// smem = 2*4*128*40*2 = 81920 -> 2 CTAs/SM.
#define GEMM_SMEM (2*4*128*KSTG*2)
__global__ __launch_bounds__(256, 2) void mma_gemm(float* __restrict__ outp, int mode)
{
    extern __shared__ bf16 sm[];
    const int t = threadIdx.x, w = t >> 5, lane = t & 31;
    const int g = lane >> 2, tg = lane & 3;
    const int G = lane >> 3, rr = lane & 7;
    const int wm = w >> 2, wn = w & 3;
    const int row0 = blockIdx.y * 128, col0 = blockIdx.x * 128;
    const int mat = blockIdx.z;
    const int lr = t >> 1, lh = t & 1;   // loader: row 0..127, 16-col half

    const bf16 *Agh, *Agl;
    if (mode == 0) { Agh = g_Ahi + (size_t)mat*NROWS*ND; Agl = g_Alo + (size_t)mat*NROWS*ND; }
    else           { Agh = g_Ohi; Agl = g_Olo; }
    const int wmat = (mode == 0) ? mat : 2;
    const bf16* Wh = g_WThi + (size_t)wmat*ND*ND;
    const bf16* Wl = g_WTlo + (size_t)wmat*ND*ND;

    const uint32_t smb = smem_u32(sm);
#define GARR(s, a) (smb + (uint32_t)(((s)*4 + (a)) * 128 * KSTG * 2))

#define GEMM_LOAD(k0, s) do {                                                   \
    const bf16* _g0 = Agh + (size_t)(row0+lr)*ND + (k0) + lh*16;                \
    const bf16* _g1 = Agl + (size_t)(row0+lr)*ND + (k0) + lh*16;                \
    const bf16* _g2 = Wh  + (size_t)(col0+lr)*ND + (k0) + lh*16;                \
    const bf16* _g3 = Wl  + (size_t)(col0+lr)*ND + (k0) + lh*16;                \
    uint32_t _sd = (uint32_t)(lr*KSTG + lh*16)*2;                               \
    CPA(GARR(s,0) + _sd,      _g0);     CPA(GARR(s,0) + _sd + 16, _g0 + 8);     \
    CPA(GARR(s,1) + _sd,      _g1);     CPA(GARR(s,1) + _sd + 16, _g1 + 8);     \
    CPA(GARR(s,2) + _sd,      _g2);     CPA(GARR(s,2) + _sd + 16, _g2 + 8);     \
    CPA(GARR(s,3) + _sd,      _g3);     CPA(GARR(s,3) + _sd + 16, _g3 + 8);     \
    } while (0)

    float acc[4][4][4] = {};

    GEMM_LOAD(0, 0);  CPCOMMIT();
    GEMM_LOAD(32, 1); CPCOMMIT();

    for (int c = 0; c < 16; c++) {
        const int s = c & 1;
        if (c < 15) CPWAIT(1); else CPWAIT(0);
        __syncthreads();                        // chunk c resident

        #pragma unroll
        for (int kf = 0; kf < 2; kf++) {
            uint32_t ah[4][4], al[4][4];
            #pragma unroll
            for (int mf = 0; mf < 4; mf++) {
                uint32_t r = wm*64 + mf*16 + (G & 1)*8 + rr;
                uint32_t cc = kf*16 + (G >> 1)*8;
                ldsm4(ah[mf], GARR(s,0) + (r*KSTG + cc)*2);
                ldsm4(al[mf], GARR(s,1) + (r*KSTG + cc)*2);
            }
            uint32_t bhv[2][4], blv[2][4];
            #pragma unroll
            for (int n2 = 0; n2 < 2; n2++) {
                uint32_t r = wn*32 + n2*16 + (G >> 1)*8 + rr;
                uint32_t cc = kf*16 + (G & 1)*8;
                ldsm4(bhv[n2], GARR(s,2) + (r*KSTG + cc)*2);
                ldsm4(blv[n2], GARR(s,3) + (r*KSTG + cc)*2);
            }
            #pragma unroll
            for (int mf = 0; mf < 4; mf++)
                #pragma unroll
                for (int nf = 0; nf < 4; nf++) {
                    const uint32_t* bh2 = &bhv[nf>>1][(nf&1)*2];
                    const uint32_t* bl2 = &blv[nf>>1][(nf&1)*2];
                    mma16816(acc[mf][nf], ah[mf], bh2);
                    mma16816(acc[mf][nf], ah[mf], bl2);
                    mma16816(acc[mf][nf], al[mf], bh2);
                }
        }
        __syncthreads();                        // stage s consumed
        if (c + 2 < 16) { GEMM_LOAD((c+2)*32, s); CPCOMMIT(); }
    }

    bf16 *OH = nullptr, *OL = nullptr;
    if (mode == 0) {
        if (mat == 0)      { OH = g_Qhi; OL = g_Qlo; }
        else if (mat == 1) { OH = g_Khi; OL = g_Klo; }
        else               { OH = g_Vhi; OL = g_Vlo; }
    }
    #pragma unroll
    for (int mf = 0; mf < 4; mf++)
        #pragma unroll
        for (int nf = 0; nf < 4; nf++) {
            const int cc = col0 + wn*32 + nf*8 + tg*2;
            #pragma unroll
            for (int rr2 = 0; rr2 < 2; rr2++) {
                const int r = row0 + wm*64 + mf*16 + g + rr2*8;
                float x0 = acc[mf][nf][rr2*2], x1 = acc[mf][nf][rr2*2+1];
                if (mode == 0) {
                    int b = r >> 11, sN = r & 2047, h = cc >> 6, d = cc & 63;
                    size_t idx = (((size_t)(b*NH + h))*NS + sN)*NHD + d;
                    float h0 = __bfloat162float(__float2bfloat16(x0));
                    float h1 = __bfloat162float(__float2bfloat16(x1));
                    *(uint32_t*)&OH[idx] = packb(x0, x1);
                    *(uint32_t*)&OL[idx] = packb(x0 - h0, x1 - h1);
                } else {
                    *(float2*)&outp[(size_t)r*ND + cc] = make_float2(x0, x1);
                }
            }
        }
}

// ---------------- attention: 64-row k-tiles, 2-stage, 2 CTAs/SM -------------
// grid (16, 32): 128 q-rows per CTA. smem = 2 stages * 4 arrays * 64*72*2 = 73728.
#define ATTN_SMEM (2*4*64*KSTA*2)
__global__ __launch_bounds__(256, 2) void attn_kernel()
{
    extern __shared__ bf16 sm[];
    const int t = threadIdx.x, w = t >> 5, lane = t & 31;
    const int g = lane >> 2, tg = lane & 3;
    const int G = lane >> 3, rr = lane & 7;
    const int bh = blockIdx.y, q0 = blockIdx.x * 128;
    const size_t base = (size_t)bh * NS * NHD;
    const int alr = t >> 2, alc = (t & 3) * 16;      // k/v loader: row 0..63, 16-col group

    const uint32_t smb = smem_u32(sm);
#define AARR(s, a) (smb + (uint32_t)(((s)*4 + (a)) * 64 * KSTA * 2))

#define ATTN_LOAD(j0, s) do {                                                   \
    const bf16* _g0 = g_Khi + base + (size_t)((j0)+alr)*NHD + alc;              \
    const bf16* _g1 = g_Klo + base + (size_t)((j0)+alr)*NHD + alc;              \
    const bf16* _g2 = g_Vhi + base + (size_t)((j0)+alr)*NHD + alc;              \
    const bf16* _g3 = g_Vlo + base + (size_t)((j0)+alr)*NHD + alc;              \
    uint32_t _sd = (uint32_t)(alr*KSTA + alc)*2;                                \
    CPA(AARR(s,0) + _sd,      _g0);     CPA(AARR(s,0) + _sd + 16, _g0 + 8);     \
    CPA(AARR(s,1) + _sd,      _g1);     CPA(AARR(s,1) + _sd + 16, _g1 + 8);     \
    CPA(AARR(s,2) + _sd,      _g2);     CPA(AARR(s,2) + _sd + 16, _g2 + 8);     \
    CPA(AARR(s,3) + _sd,      _g3);     CPA(AARR(s,3) + _sd + 16, _g3 + 8);     \
    } while (0)

    // ---- stage Q (128 rows hi/lo) through stage-0 arrays, extract frags ----
    {
        const int qlr = t >> 1, qlh = t & 1;         // row 0..127, 32-col half
        const bf16* q_h = g_Qhi + base + (size_t)(q0+qlr)*NHD + qlh*32;
        const bf16* q_l = g_Qlo + base + (size_t)(q0+qlr)*NHD + qlh*32;
        uint32_t hi_d = AARR(0, qlr>>6)     + (uint32_t)((qlr&63)*KSTA + qlh*32)*2;
        uint32_t lo_d = AARR(0, 2+(qlr>>6)) + (uint32_t)((qlr&63)*KSTA + qlh*32)*2;
        #pragma unroll
        for (int v = 0; v < 4; v++) {
            CPA(hi_d + v*16, q_h + v*8);
            CPA(lo_d + v*16, q_l + v*8);
        }
        CPCOMMIT();
    }
    CPWAIT(0);
    __syncthreads();

    uint32_t qh[4][4], ql[4][4];
    {
        const uint32_t r = w*16 + (G & 1)*8 + rr;    // 0..127; 16-row band per warp
        const uint32_t arr = r >> 6, ir = r & 63;
        #pragma unroll
        for (int kf = 0; kf < 4; kf++) {
            uint32_t cc = kf*16 + (G >> 1)*8;
            ldsm4(qh[kf], AARR(0, arr)   + (ir*KSTA + cc)*2);
            ldsm4(ql[kf], AARR(0, 2+arr) + (ir*KSTA + cc)*2);
        }
    }
    __syncthreads();                                 // everyone done reading Q

    ATTN_LOAD(0, 0);  CPCOMMIT();
    ATTN_LOAD(64, 1); CPCOMMIT();

    float oacc[8][4] = {};
    float lsum[2] = {0.f, 0.f};

    for (int j = 0; j < 32; j++) {
        const int s = j & 1;
        if (j < 31) CPWAIT(1); else CPWAIT(0);
        __syncthreads();                             // tile j resident

        // ---- S = Q @ K^T over 64 k-rows ----
        float c[8][4] = {};
        #pragma unroll
        for (int kf = 0; kf < 4; kf++) {
            #pragma unroll
            for (int n2 = 0; n2 < 4; n2++) {
                uint32_t brow = n2*16 + (G >> 1)*8 + rr;
                uint32_t bcol = kf*16 + (G & 1)*8;
                uint32_t kb[4], klb[4];
                ldsm4(kb,  AARR(s,0) + (brow*KSTA + bcol)*2);
                ldsm4(klb, AARR(s,1) + (brow*KSTA + bcol)*2);
                mma16816(c[n2*2],   qh[kf], &kb[0]);
                mma16816(c[n2*2],   qh[kf], &klb[0]);
                mma16816(c[n2*2],   ql[kf], &kb[0]);
                mma16816(c[n2*2+1], qh[kf], &kb[2]);
                mma16816(c[n2*2+1], qh[kf], &klb[2]);
                mma16816(c[n2*2+1], ql[kf], &kb[2]);
            }
        }
        // scale + ReLU + exp (bounded scores: no online max needed)
        #pragma unroll
        for (int nf = 0; nf < 8; nf++)
            #pragma unroll
            for (int i = 0; i < 4; i++) {
                float p = __expf(fmaxf(c[nf][i]*0.125f, 0.f));
                c[nf][i] = p;
                lsum[i>>1] += p;
            }
        // pack P (C-frag layout == A-frag layout), hi/lo split
        uint32_t ph[4][4], pl[4][4];
        #pragma unroll
        for (int kq = 0; kq < 4; kq++)
            #pragma unroll
            for (int half = 0; half < 2; half++) {
                const float* cv = c[2*kq + half];
                float h0 = __bfloat162float(__float2bfloat16(cv[0]));
                float h1 = __bfloat162float(__float2bfloat16(cv[1]));
                float h2 = __bfloat162float(__float2bfloat16(cv[2]));
                float h3 = __bfloat162float(__float2bfloat16(cv[3]));
                ph[kq][2*half+0] = packb(cv[0], cv[1]);
                ph[kq][2*half+1] = packb(cv[2], cv[3]);
                pl[kq][2*half+0] = packb(cv[0]-h0, cv[1]-h1);
                pl[kq][2*half+1] = packb(cv[2]-h2, cv[3]-h3);
            }
        // ---- O += P @ V (V row-major; ldmatrix.trans -> B-frags) ----
        #pragma unroll
        for (int kq = 0; kq < 4; kq++) {
            #pragma unroll
            for (int d2 = 0; d2 < 4; d2++) {
                uint32_t vrow = kq*16 + (G & 1)*8 + rr;
                uint32_t vcol = d2*16 + (G >> 1)*8;
                uint32_t vb[4], vlb[4];
                ldsm4t(vb,  AARR(s,2) + (vrow*KSTA + vcol)*2);
                ldsm4t(vlb, AARR(s,3) + (vrow*KSTA + vcol)*2);
                mma16816(oacc[d2*2],   ph[kq], &vb[0]);
                mma16816(oacc[d2*2],   pl[kq], &vb[0]);
                mma16816(oacc[d2*2],   ph[kq], &vlb[0]);
                mma16816(oacc[d2*2+1], ph[kq], &vb[2]);
                mma16816(oacc[d2*2+1], pl[kq], &vb[2]);
                mma16816(oacc[d2*2+1], ph[kq], &vlb[2]);
            }
        }

        __syncthreads();                             // stage s consumed
        if (j + 2 < 32) { ATTN_LOAD((j+2)*64, s); CPCOMMIT(); }
    }

    #pragma unroll
    for (int i = 0; i < 2; i++) {
        lsum[i] += __shfl_xor_sync(0xffffffffu, lsum[i], 1);
        lsum[i] += __shfl_xor_sync(0xffffffffu, lsum[i], 2);
    }
    const float inv0 = 1.f / lsum[0], inv1 = 1.f / lsum[1];

    const int b = bh >> 3, h = bh & 7;
    #pragma unroll
    for (int nf = 0; nf < 8; nf++) {
        const int col = h*NHD + nf*8 + tg*2;
        #pragma unroll
        for (int rr2 = 0; rr2 < 2; rr2++) {
            const int srow = q0 + w*16 + g + rr2*8;
            const float inv = rr2 ? inv1 : inv0;
            float x0 = oacc[nf][rr2*2]*inv, x1 = oacc[nf][rr2*2+1]*inv;
            float h0 = __bfloat162float(__float2bfloat16(x0));
            float h1 = __bfloat162float(__float2bfloat16(x1));
            size_t idx = ((size_t)(b*NS + srow))*ND + col;
            *(uint32_t*)&g_Ohi[idx] = packb(x0, x1);
            *(uint32_t*)&g_Olo[idx] = packb(x0 - h0, x1 - h1);
        }
    }
}

// ---------------------------------------------------------------------------
extern "C" void kernel_launch(void* const* d_in, const int* in_sizes, int n_in,
                              void* d_out, int out_size)
{
    const float* X  = (const float*)d_in[0];
    const float* Y  = (const float*)d_in[1];
    const float* Z  = (const float*)d_in[2];
    const float* Wq = (const float*)d_in[3];
    const float* Wk = (const float*)d_in[4];
    /* d_in[5] = Wv unused (reference uses Wo for V projection) */
    const float* Wo = (const float*)d_in[6];
    float* out = (float*)d_out;

    static bool attr_done = false;
    if (!attr_done) {
        cudaFuncSetAttribute(mma_gemm,    cudaFuncAttributeMaxDynamicSharedMemorySize, GEMM_SMEM);
        cudaFuncSetAttribute(attn_kernel, cudaFuncAttributeMaxDynamicSharedMemorySize, ATTN_SMEM);
        attr_done = true;
    }

    convert_wt<<<dim3(16, 16, 3), 256>>>(Wq, Wk, Wo);
    convert_act<<<NROWS*ND/4/256, 256>>>((const float4*)X, 0);
    convert_act<<<NROWS*ND/4/256, 256>>>((const float4*)Y, 1);
    convert_act<<<NROWS*ND/4/256, 256>>>((const float4*)Z, 2);
    mma_gemm<<<dim3(4, 64, 3), 256, GEMM_SMEM>>>(nullptr, 0);   // Q,K,V projections
    attn_kernel<<<dim3(16, 32), 256, ATTN_SMEM>>>();            // fused attention
    mma_gemm<<<dim3(4, 64, 1), 256, GEMM_SMEM>>>(out, 1);       // O @ Wo
}

// round 12
// speedup vs baseline: 3.6526x; 1.1568x over previous
#include <cuda_runtime.h>
#include <cuda_bf16.h>
#include <cstdint>

#define NB  4
#define NS  2048
#define ND  512
#define NH  8
#define NHD 64
#define NROWS (NB*NS)   // 8192
#define KSTA 72         // attn smem row stride (144B) — ldmatrix conflict-free
#define KSTG 40         // gemm smem row stride (80B)  — ldmatrix conflict-free

typedef __nv_bfloat16 bf16;

// ---------------- device-global scratch -------------------------------------
__device__ bf16 g_Ahi[3ull*NROWS*ND], g_Alo[3ull*NROWS*ND];
__device__ bf16 g_WThi[3ull*ND*ND],   g_WTlo[3ull*ND*ND];
__device__ bf16 g_Qhi[(size_t)NROWS*ND], g_Qlo[(size_t)NROWS*ND];  // [B,H,S,64]
__device__ bf16 g_Khi[(size_t)NROWS*ND], g_Klo[(size_t)NROWS*ND];
__device__ bf16 g_Vhi[(size_t)NROWS*ND], g_Vlo[(size_t)NROWS*ND];
__device__ bf16 g_Ohi[(size_t)NROWS*ND], g_Olo[(size_t)NROWS*ND];
__device__ float g_Vsum[NB*NH*NHD];   // exact per-(b,h) column sums of V

// ---------------- helpers ----------------------------------------------------
__device__ __forceinline__ void mma16816(float c[4], const uint32_t a[4], const uint32_t b[2]) {
    asm volatile("mma.sync.aligned.m16n8k16.row.col.f32.bf16.bf16.f32 "
        "{%0,%1,%2,%3}, {%4,%5,%6,%7}, {%8,%9}, {%0,%1,%2,%3};"
        : "+f"(c[0]), "+f"(c[1]), "+f"(c[2]), "+f"(c[3])
        : "r"(a[0]), "r"(a[1]), "r"(a[2]), "r"(a[3]), "r"(b[0]), "r"(b[1]));
}
__device__ __forceinline__ uint32_t packb(float x, float y) {
    __nv_bfloat162 h = __floats2bfloat162_rn(x, y);
    return *(uint32_t*)&h;
}
__device__ __forceinline__ uint32_t smem_u32(const void* p) {
    uint32_t a;
    asm("{ .reg .u64 t; cvta.to.shared.u64 t, %1; cvt.u32.u64 %0, t; }" : "=r"(a) : "l"(p));
    return a;
}
__device__ __forceinline__ void ldsm4(uint32_t r[4], uint32_t addr) {
    asm volatile("ldmatrix.sync.aligned.m8n8.x4.shared.b16 {%0,%1,%2,%3}, [%4];"
        : "=r"(r[0]), "=r"(r[1]), "=r"(r[2]), "=r"(r[3]) : "r"(addr));
}
__device__ __forceinline__ void ldsm4t(uint32_t r[4], uint32_t addr) {
    asm volatile("ldmatrix.sync.aligned.m8n8.x4.trans.shared.b16 {%0,%1,%2,%3}, [%4];"
        : "=r"(r[0]), "=r"(r[1]), "=r"(r[2]), "=r"(r[3]) : "r"(addr));
}
#define CPA(sd, gs) \
    asm volatile("cp.async.cg.shared.global [%0], [%1], 16;" :: "r"(sd), "l"(gs) : "memory")
#define CPCOMMIT() asm volatile("cp.async.commit_group;" ::: "memory")
#define CPWAIT(n)  asm volatile("cp.async.wait_group %0;" :: "n"(n) : "memory")

// ---------------- converts ---------------------------------------------------
__global__ __launch_bounds__(256) void convert_act(const float4* __restrict__ src, int which)
{
    size_t i = (size_t)blockIdx.x * 256 + threadIdx.x;
    bf16* hi = g_Ahi + (size_t)which*NROWS*ND;
    bf16* lo = g_Alo + (size_t)which*NROWS*ND;
    float4 v = src[i];
    float x[4] = {v.x, v.y, v.z, v.w};
    unsigned short h[4], l[4];
    #pragma unroll
    for (int j = 0; j < 4; j++) {
        bf16 hb = __float2bfloat16(x[j]);
        h[j] = __bfloat16_as_ushort(hb);
        l[j] = __bfloat16_as_ushort(__float2bfloat16(x[j] - __bfloat162float(hb)));
    }
    *(ushort4*)((unsigned short*)hi + 4*i) = make_ushort4(h[0],h[1],h[2],h[3]);
    *(ushort4*)((unsigned short*)lo + 4*i) = make_ushort4(l[0],l[1],l[2],l[3]);
}
__global__ __launch_bounds__(256) void convert_wt(
    const float* __restrict__ Wq, const float* __restrict__ Wk, const float* __restrict__ Wo)
{
    __shared__ float tile[32][33];
    const int z = blockIdx.z;
    const float* W = (z == 0) ? Wq : (z == 1) ? Wk : Wo;
    const int tx = threadIdx.x & 31, ty = threadIdx.x >> 5;
    const int x0 = blockIdx.x * 32, y0 = blockIdx.y * 32;
    #pragma unroll
    for (int i = ty; i < 32; i += 8)
        tile[i][tx] = W[(size_t)(y0 + i) * ND + x0 + tx];
    __syncthreads();
    bf16* hi = g_WThi + (size_t)z*ND*ND;
    bf16* lo = g_WTlo + (size_t)z*ND*ND;
    #pragma unroll
    for (int i = ty; i < 32; i += 8) {
        float x = tile[tx][i];
        bf16 hb = __float2bfloat16(x);
        hi[(size_t)(x0 + i) * ND + y0 + tx] = hb;
        lo[(size_t)(x0 + i) * ND + y0 + tx] = __float2bfloat16(x - __bfloat162float(hb));
    }
}

// exact fp32 column-sums of V per (b,h): Vsum[d] = sum_i (vhi+vlo)[i][d]
__global__ __launch_bounds__(256) void vsum_kernel()
{
    __shared__ float acc[4][64];
    const int bh = blockIdx.x;
    const int d = threadIdx.x & 63, q = threadIdx.x >> 6;
    const bf16* vh = g_Vhi + (size_t)bh*NS*NHD;
    const bf16* vl = g_Vlo + (size_t)bh*NS*NHD;
    float s = 0.f;
    for (int i = q*512; i < q*512 + 512; i++)
        s += __bfloat162float(vh[(size_t)i*NHD + d]) + __bfloat162float(vl[(size_t)i*NHD + d]);
    acc[q][d] = s;
    __syncthreads();
    if (q == 0)
        g_Vsum[bh*64 + d] = acc[0][d] + acc[1][d] + acc[2][d] + acc[3][d];
}

// ---------------- mma.sync GEMM: C[8192,512] = A @ W ------------------------
#define GEMM_SMEM (2*4*128*KSTG*2)
__global__ __launch_bounds__(256, 2) void mma_gemm(float* __restrict__ outp, int mode)
{
    extern __shared__ bf16 sm[];
    const int t = threadIdx.x, w = t >> 5, lane = t & 31;
    const int g = lane >> 2, tg = lane & 3;
    const int G = lane >> 3, rr = lane & 7;
    const int wm = w >> 2, wn = w & 3;
    const int row0 = blockIdx.y * 128, col0 = blockIdx.x * 128;
    const int mat = blockIdx.z;
    const int lr = t >> 1, lh = t & 1;

    const bf16 *Agh, *Agl;
    if (mode == 0) { Agh = g_Ahi + (size_t)mat*NROWS*ND; Agl = g_Alo + (size_t)mat*NROWS*ND; }
    else           { Agh = g_Ohi; Agl = g_Olo; }
    const int wmat = (mode == 0) ? mat : 2;
    const bf16* Wh = g_WThi + (size_t)wmat*ND*ND;
    const bf16* Wl = g_WTlo + (size_t)wmat*ND*ND;

    const uint32_t smb = smem_u32(sm);
#define GARR(s, a) (smb + (uint32_t)(((s)*4 + (a)) * 128 * KSTG * 2))

#define GEMM_LOAD(k0, s) do {                                                   \
    const bf16* _g0 = Agh + (size_t)(row0+lr)*ND + (k0) + lh*16;                \
    const bf16* _g1 = Agl + (size_t)(row0+lr)*ND + (k0) + lh*16;                \
    const bf16* _g2 = Wh  + (size_t)(col0+lr)*ND + (k0) + lh*16;                \
    const bf16* _g3 = Wl  + (size_t)(col0+lr)*ND + (k0) + lh*16;                \
    uint32_t _sd = (uint32_t)(lr*KSTG + lh*16)*2;                               \
    CPA(GARR(s,0) + _sd,      _g0);     CPA(GARR(s,0) + _sd + 16, _g0 + 8);     \
    CPA(GARR(s,1) + _sd,      _g1);     CPA(GARR(s,1) + _sd + 16, _g1 + 8);     \
    CPA(GARR(s,2) + _sd,      _g2);     CPA(GARR(s,2) + _sd + 16, _g2 + 8);     \
    CPA(GARR(s,3) + _sd,      _g3);     CPA(GARR(s,3) + _sd + 16, _g3 + 8);     \
    } while (0)

    float acc[4][4][4] = {};

    GEMM_LOAD(0, 0);  CPCOMMIT();
    GEMM_LOAD(32, 1); CPCOMMIT();

    for (int c = 0; c < 16; c++) {
        const int s = c & 1;
        if (c < 15) CPWAIT(1); else CPWAIT(0);
        __syncthreads();

        #pragma unroll
        for (int kf = 0; kf < 2; kf++) {
            uint32_t ah[4][4], al[4][4];
            #pragma unroll
            for (int mf = 0; mf < 4; mf++) {
                uint32_t r = wm*64 + mf*16 + (G & 1)*8 + rr;
                uint32_t cc = kf*16 + (G >> 1)*8;
                ldsm4(ah[mf], GARR(s,0) + (r*KSTG + cc)*2);
                ldsm4(al[mf], GARR(s,1) + (r*KSTG + cc)*2);
            }
            uint32_t bhv[2][4], blv[2][4];
            #pragma unroll
            for (int n2 = 0; n2 < 2; n2++) {
                uint32_t r = wn*32 + n2*16 + (G >> 1)*8 + rr;
                uint32_t cc = kf*16 + (G & 1)*8;
                ldsm4(bhv[n2], GARR(s,2) + (r*KSTG + cc)*2);
                ldsm4(blv[n2], GARR(s,3) + (r*KSTG + cc)*2);
            }
            #pragma unroll
            for (int mf = 0; mf < 4; mf++)
                #pragma unroll
                for (int nf = 0; nf < 4; nf++) {
                    const uint32_t* bh2 = &bhv[nf>>1][(nf&1)*2];
                    const uint32_t* bl2 = &blv[nf>>1][(nf&1)*2];
                    mma16816(acc[mf][nf], ah[mf], bh2);
                    mma16816(acc[mf][nf], ah[mf], bl2);
                    mma16816(acc[mf][nf], al[mf], bh2);
                }
        }
        __syncthreads();
        if (c + 2 < 16) { GEMM_LOAD((c+2)*32, s); CPCOMMIT(); }
    }

    bf16 *OH = nullptr, *OL = nullptr;
    if (mode == 0) {
        if (mat == 0)      { OH = g_Qhi; OL = g_Qlo; }
        else if (mat == 1) { OH = g_Khi; OL = g_Klo; }
        else               { OH = g_Vhi; OL = g_Vlo; }
    }
    #pragma unroll
    for (int mf = 0; mf < 4; mf++)
        #pragma unroll
        for (int nf = 0; nf < 4; nf++) {
            const int cc = col0 + wn*32 + nf*8 + tg*2;
            #pragma unroll
            for (int rr2 = 0; rr2 < 2; rr2++) {
                const int r = row0 + wm*64 + mf*16 + g + rr2*8;
                float x0 = acc[mf][nf][rr2*2], x1 = acc[mf][nf][rr2*2+1];
                if (mode == 0) {
                    int b = r >> 11, sN = r & 2047, h = cc >> 6, d = cc & 63;
                    size_t idx = (((size_t)(b*NH + h))*NS + sN)*NHD + d;
                    float h0 = __bfloat162float(__float2bfloat16(x0));
                    float h1 = __bfloat162float(__float2bfloat16(x1));
                    *(uint32_t*)&OH[idx] = packb(x0, x1);
                    *(uint32_t*)&OL[idx] = packb(x0 - h0, x1 - h1);
                } else {
                    *(float2*)&outp[(size_t)r*ND + cc] = make_float2(x0, x1);
                }
            }
        }
}

// ---------------- attention: P = 1 + P' decomposition -----------------------
// O_unnorm = Vsum (exact fp32) + P'@V, P' = expm1(relu(s)) in [0, ~0.4].
// S = Q@K^T stays 3-term bf16 split; P'@V is a single bf16 MMA (error ~1e-4).
// smem: 2 stages x 3 arrays (Khi, Klo, Vhi) x 64 x KSTA. 2 CTAs/SM.
#define ATTN_SMEM (2*3*64*KSTA*2)
__global__ __launch_bounds__(256, 2) void attn_kernel()
{
    extern __shared__ bf16 sm[];
    const int t = threadIdx.x, w = t >> 5, lane = t & 31;
    const int g = lane >> 2, tg = lane & 3;
    const int G = lane >> 3, rr = lane & 7;
    const int bh = blockIdx.y, q0 = blockIdx.x * 128;
    const size_t base = (size_t)bh * NS * NHD;
    const int alr = t >> 2, alc = (t & 3) * 16;

    const uint32_t smb = smem_u32(sm);
#define AARR(s, a) (smb + (uint32_t)(((s)*3 + (a)) * 64 * KSTA * 2))

#define ATTN_LOAD(j0, s) do {                                                   \
    const bf16* _g0 = g_Khi + base + (size_t)((j0)+alr)*NHD + alc;              \
    const bf16* _g1 = g_Klo + base + (size_t)((j0)+alr)*NHD + alc;              \
    const bf16* _g2 = g_Vhi + base + (size_t)((j0)+alr)*NHD + alc;              \
    uint32_t _sd = (uint32_t)(alr*KSTA + alc)*2;                                \
    CPA(AARR(s,0) + _sd,      _g0);     CPA(AARR(s,0) + _sd + 16, _g0 + 8);     \
    CPA(AARR(s,1) + _sd,      _g1);     CPA(AARR(s,1) + _sd + 16, _g1 + 8);     \
    CPA(AARR(s,2) + _sd,      _g2);     CPA(AARR(s,2) + _sd + 16, _g2 + 8);     \
    } while (0)

    // ---- stage Q (128 rows hi/lo) through the first 4 array slots ----------
    {
        const int qlr = t >> 1, qlh = t & 1;
        const bf16* q_h = g_Qhi + base + (size_t)(q0+qlr)*NHD + qlh*32;
        const bf16* q_l = g_Qlo + base + (size_t)(q0+qlr)*NHD + qlh*32;
        uint32_t hi_d = AARR(0, qlr>>6)     + (uint32_t)((qlr&63)*KSTA + qlh*32)*2;
        uint32_t lo_d = AARR(0, 2+(qlr>>6)) + (uint32_t)((qlr&63)*KSTA + qlh*32)*2;
        #pragma unroll
        for (int v = 0; v < 4; v++) {
            CPA(hi_d + v*16, q_h + v*8);
            CPA(lo_d + v*16, q_l + v*8);
        }
        CPCOMMIT();
    }
    CPWAIT(0);
    __syncthreads();

    uint32_t qh[4][4], ql[4][4];
    {
        const uint32_t r = w*16 + (G & 1)*8 + rr;
        const uint32_t arr = r >> 6, ir = r & 63;
        #pragma unroll
        for (int kf = 0; kf < 4; kf++) {
            uint32_t cc = kf*16 + (G >> 1)*8;
            ldsm4(qh[kf], AARR(0, arr)   + (ir*KSTA + cc)*2);
            ldsm4(ql[kf], AARR(0, 2+arr) + (ir*KSTA + cc)*2);
        }
    }
    __syncthreads();

    ATTN_LOAD(0, 0);  CPCOMMIT();
    ATTN_LOAD(64, 1); CPCOMMIT();

    float oacc[8][4] = {};
    float lsum[2] = {0.f, 0.f};

    for (int j = 0; j < 32; j++) {
        const int s = j & 1;
        if (j < 31) CPWAIT(1); else CPWAIT(0);
        __syncthreads();

        // ---- S = Q @ K^T (3-term split) ----
        float c[8][4] = {};
        #pragma unroll
        for (int kf = 0; kf < 4; kf++) {
            #pragma unroll
            for (int n2 = 0; n2 < 4; n2++) {
                uint32_t brow = n2*16 + (G >> 1)*8 + rr;
                uint32_t bcol = kf*16 + (G & 1)*8;
                uint32_t kb[4], klb[4];
                ldsm4(kb,  AARR(s,0) + (brow*KSTA + bcol)*2);
                ldsm4(klb, AARR(s,1) + (brow*KSTA + bcol)*2);
                mma16816(c[n2*2],   qh[kf], &kb[0]);
                mma16816(c[n2*2],   qh[kf], &klb[0]);
                mma16816(c[n2*2],   ql[kf], &kb[0]);
                mma16816(c[n2*2+1], qh[kf], &kb[2]);
                mma16816(c[n2*2+1], qh[kf], &klb[2]);
                mma16816(c[n2*2+1], ql[kf], &kb[2]);
            }
        }
        // ---- P' = expm1(relu(s/8)); accumulate row sums of P' ----
        #pragma unroll
        for (int nf = 0; nf < 8; nf++)
            #pragma unroll
            for (int i = 0; i < 4; i++) {
                float p = __expf(fmaxf(c[nf][i]*0.125f, 0.f)) - 1.0f;
                c[nf][i] = p;
                lsum[i>>1] += p;
            }
        // ---- pack P' (C-frag layout == A-frag layout), single bf16 ----
        uint32_t ph[4][4];
        #pragma unroll
        for (int kq = 0; kq < 4; kq++)
            #pragma unroll
            for (int half = 0; half < 2; half++) {
                const float* cv = c[2*kq + half];
                ph[kq][2*half+0] = packb(cv[0], cv[1]);
                ph[kq][2*half+1] = packb(cv[2], cv[3]);
            }
        // ---- O += P' @ Vhi (single-term) ----
        #pragma unroll
        for (int kq = 0; kq < 4; kq++) {
            #pragma unroll
            for (int d2 = 0; d2 < 4; d2++) {
                uint32_t vrow = kq*16 + (G & 1)*8 + rr;
                uint32_t vcol = d2*16 + (G >> 1)*8;
                uint32_t vb[4];
                ldsm4t(vb, AARR(s,2) + (vrow*KSTA + vcol)*2);
                mma16816(oacc[d2*2],   ph[kq], &vb[0]);
                mma16816(oacc[d2*2+1], ph[kq], &vb[2]);
            }
        }

        __syncthreads();
        if (j + 2 < 32) { ATTN_LOAD((j+2)*64, s); CPCOMMIT(); }
    }

    #pragma unroll
    for (int i = 0; i < 2; i++) {
        lsum[i] += __shfl_xor_sync(0xffffffffu, lsum[i], 1);
        lsum[i] += __shfl_xor_sync(0xffffffffu, lsum[i], 2);
    }
    const float inv0 = 1.f / (2048.f + lsum[0]);
    const float inv1 = 1.f / (2048.f + lsum[1]);

    const int b = bh >> 3, h = bh & 7;
    const float* vs = &g_Vsum[bh*64];
    #pragma unroll
    for (int nf = 0; nf < 8; nf++) {
        const int d = nf*8 + tg*2;               // head-local column
        const int col = h*NHD + d;               // merged-D column
        const float2 v2 = *(const float2*)&vs[d];
        #pragma unroll
        for (int rr2 = 0; rr2 < 2; rr2++) {
            const int srow = q0 + w*16 + g + rr2*8;
            const float inv = rr2 ? inv1 : inv0;
            float x0 = (oacc[nf][rr2*2]   + v2.x) * inv;
            float x1 = (oacc[nf][rr2*2+1] + v2.y) * inv;
            float h0 = __bfloat162float(__float2bfloat16(x0));
            float h1 = __bfloat162float(__float2bfloat16(x1));
            size_t idx = ((size_t)(b*NS + srow))*ND + col;
            *(uint32_t*)&g_Ohi[idx] = packb(x0, x1);
            *(uint32_t*)&g_Olo[idx] = packb(x0 - h0, x1 - h1);
        }
    }
}

// ---------------------------------------------------------------------------
extern "C" void kernel_launch(void* const* d_in, const int* in_sizes, int n_in,
                              void* d_out, int out_size)
{
    const float* X  = (const float*)d_in[0];
    const float* Y  = (const float*)d_in[1];
    const float* Z  = (const float*)d_in[2];
    const float* Wq = (const float*)d_in[3];
    const float* Wk = (const float*)d_in[4];
    /* d_in[5] = Wv unused (reference uses Wo for V projection) */
    const float* Wo = (const float*)d_in[6];
    float* out = (float*)d_out;

    static bool attr_done = false;
    if (!attr_done) {
        cudaFuncSetAttribute(mma_gemm,    cudaFuncAttributeMaxDynamicSharedMemorySize, GEMM_SMEM);
        cudaFuncSetAttribute(attn_kernel, cudaFuncAttributeMaxDynamicSharedMemorySize, ATTN_SMEM);
        attr_done = true;
    }

    convert_wt<<<dim3(16, 16, 3), 256>>>(Wq, Wk, Wo);
    convert_act<<<NROWS*ND/4/256, 256>>>((const float4*)X, 0);
    convert_act<<<NROWS*ND/4/256, 256>>>((const float4*)Y, 1);
    convert_act<<<NROWS*ND/4/256, 256>>>((const float4*)Z, 2);
    mma_gemm<<<dim3(4, 64, 3), 256, GEMM_SMEM>>>(nullptr, 0);   // Q,K,V projections
    vsum_kernel<<<32, 256>>>();                                  // exact V column sums
    attn_kernel<<<dim3(16, 32), 256, ATTN_SMEM>>>();             // fused attention
    mma_gemm<<<dim3(4, 64, 1), 256, GEMM_SMEM>>>(out, 1);        // O @ Wo
}

// round 15
// speedup vs baseline: 4.6753x; 1.2800x over previous
#include <cuda_runtime.h>
#include <cuda_bf16.h>
#include <cuda_fp16.h>
#include <cstdint>

#define NB  4
#define NS  2048
#define ND  512
#define NH  8
#define NHD 64
#define NROWS (NB*NS)   // 8192
#define KSTA 72         // attn smem row stride (144B) — ldmatrix conflict-free
#define KSTG 40         // gemm smem row stride (80B)  — ldmatrix conflict-free
#define ASTG 4          // attn pipeline stages

typedef __nv_bfloat16 bf16;

// ---------------- device-global scratch -------------------------------------
__device__ bf16 g_Ahi[3ull*NROWS*ND], g_Alo[3ull*NROWS*ND];
__device__ bf16 g_WThi[3ull*ND*ND],   g_WTlo[3ull*ND*ND];
__device__ __half g_Qf16[(size_t)NROWS*ND];   // [B,H,S,64] fp16 single
__device__ __half g_Kf16[(size_t)NROWS*ND];
__device__ __half g_Vf16[(size_t)NROWS*ND];
__device__ bf16 g_Vhi[(size_t)NROWS*ND], g_Vlo[(size_t)NROWS*ND];  // for exact Vsum
__device__ bf16 g_Ohi[(size_t)NROWS*ND], g_Olo[(size_t)NROWS*ND];
__device__ float g_Vsum[NB*NH*NHD];

// ---------------- helpers ----------------------------------------------------
__device__ __forceinline__ void mma16816(float c[4], const uint32_t a[4], const uint32_t b[2]) {
    asm volatile("mma.sync.aligned.m16n8k16.row.col.f32.bf16.bf16.f32 "
        "{%0,%1,%2,%3}, {%4,%5,%6,%7}, {%8,%9}, {%0,%1,%2,%3};"
        : "+f"(c[0]), "+f"(c[1]), "+f"(c[2]), "+f"(c[3])
        : "r"(a[0]), "r"(a[1]), "r"(a[2]), "r"(a[3]), "r"(b[0]), "r"(b[1]));
}
__device__ __forceinline__ void mma16816h(float c[4], const uint32_t a[4], const uint32_t b[2]) {
    asm volatile("mma.sync.aligned.m16n8k16.row.col.f32.f16.f16.f32 "
        "{%0,%1,%2,%3}, {%4,%5,%6,%7}, {%8,%9}, {%0,%1,%2,%3};"
        : "+f"(c[0]), "+f"(c[1]), "+f"(c[2]), "+f"(c[3])
        : "r"(a[0]), "r"(a[1]), "r"(a[2]), "r"(a[3]), "r"(b[0]), "r"(b[1]));
}
__device__ __forceinline__ uint32_t packb(float x, float y) {
    __nv_bfloat162 h = __floats2bfloat162_rn(x, y);
    return *(uint32_t*)&h;
}
__device__ __forceinline__ uint32_t packh(float x, float y) {
    __half2 h = __floats2half2_rn(x, y);
    return *(uint32_t*)&h;
}
__device__ __forceinline__ uint32_t smem_u32(const void* p) {
    uint32_t a;
    asm("{ .reg .u64 t; cvta.to.shared.u64 t, %1; cvt.u32.u64 %0, t; }" : "=r"(a) : "l"(p));
    return a;
}
__device__ __forceinline__ void ldsm4(uint32_t r[4], uint32_t addr) {
    asm volatile("ldmatrix.sync.aligned.m8n8.x4.shared.b16 {%0,%1,%2,%3}, [%4];"
        : "=r"(r[0]), "=r"(r[1]), "=r"(r[2]), "=r"(r[3]) : "r"(addr));
}
__device__ __forceinline__ void ldsm4t(uint32_t r[4], uint32_t addr) {
    asm volatile("ldmatrix.sync.aligned.m8n8.x4.trans.shared.b16 {%0,%1,%2,%3}, [%4];"
        : "=r"(r[0]), "=r"(r[1]), "=r"(r[2]), "=r"(r[3]) : "r"(addr));
}
#define CPA(sd, gs) \
    asm volatile("cp.async.cg.shared.global [%0], [%1], 16;" :: "r"(sd), "l"(gs) : "memory")
#define CPCOMMIT() asm volatile("cp.async.commit_group;" ::: "memory")
#define CPWAIT(n)  asm volatile("cp.async.wait_group %0;" :: "n"(n) : "memory")

// ---------------- converts ---------------------------------------------------
__global__ __launch_bounds__(256) void convert_act(const float4* __restrict__ src, int which)
{
    size_t i = (size_t)blockIdx.x * 256 + threadIdx.x;
    bf16* hi = g_Ahi + (size_t)which*NROWS*ND;
    bf16* lo = g_Alo + (size_t)which*NROWS*ND;
    float4 v = src[i];
    float x[4] = {v.x, v.y, v.z, v.w};
    unsigned short h[4], l[4];
    #pragma unroll
    for (int j = 0; j < 4; j++) {
        bf16 hb = __float2bfloat16(x[j]);
        h[j] = __bfloat16_as_ushort(hb);
        l[j] = __bfloat16_as_ushort(__float2bfloat16(x[j] - __bfloat162float(hb)));
    }
    *(ushort4*)((unsigned short*)hi + 4*i) = make_ushort4(h[0],h[1],h[2],h[3]);
    *(ushort4*)((unsigned short*)lo + 4*i) = make_ushort4(l[0],l[1],l[2],l[3]);
}
__global__ __launch_bounds__(256) void convert_wt(
    const float* __restrict__ Wq, const float* __restrict__ Wk, const float* __restrict__ Wo)
{
    __shared__ float tile[32][33];
    const int z = blockIdx.z;
    const float* W = (z == 0) ? Wq : (z == 1) ? Wk : Wo;
    const int tx = threadIdx.x & 31, ty = threadIdx.x >> 5;
    const int x0 = blockIdx.x * 32, y0 = blockIdx.y * 32;
    #pragma unroll
    for (int i = ty; i < 32; i += 8)
        tile[i][tx] = W[(size_t)(y0 + i) * ND + x0 + tx];
    __syncthreads();
    bf16* hi = g_WThi + (size_t)z*ND*ND;
    bf16* lo = g_WTlo + (size_t)z*ND*ND;
    #pragma unroll
    for (int i = ty; i < 32; i += 8) {
        float x = tile[tx][i];
        bf16 hb = __float2bfloat16(x);
        hi[(size_t)(x0 + i) * ND + y0 + tx] = hb;
        lo[(size_t)(x0 + i) * ND + y0 + tx] = __float2bfloat16(x - __bfloat162float(hb));
    }
}

// exact fp32 column-sums of V per (b,h)
__global__ __launch_bounds__(256) void vsum_kernel()
{
    __shared__ float acc[4][64];
    const int bh = blockIdx.x;
    const int d = threadIdx.x & 63, q = threadIdx.x >> 6;
    const bf16* vh = g_Vhi + (size_t)bh*NS*NHD;
    const bf16* vl = g_Vlo + (size_t)bh*NS*NHD;
    float s = 0.f;
    for (int i = q*512; i < q*512 + 512; i++)
        s += __bfloat162float(vh[(size_t)i*NHD + d]) + __bfloat162float(vl[(size_t)i*NHD + d]);
    acc[q][d] = s;
    __syncthreads();
    if (q == 0)
        g_Vsum[bh*64 + d] = acc[0][d] + acc[1][d] + acc[2][d] + acc[3][d];
}

// ---------------- mma.sync GEMM: C[8192,512] = A @ W (bf16 3-term) -----------
#define GEMM_SMEM (2*4*128*KSTG*2)
__global__ __launch_bounds__(256, 2) void mma_gemm(float* __restrict__ outp, int mode)
{
    extern __shared__ bf16 sm[];
    const int t = threadIdx.x, w = t >> 5, lane = t & 31;
    const int g = lane >> 2, tg = lane & 3;
    const int G = lane >> 3, rr = lane & 7;
    const int wm = w >> 2, wn = w & 3;
    const int row0 = blockIdx.y * 128, col0 = blockIdx.x * 128;
    const int mat = blockIdx.z;
    const int lr = t >> 1, lh = t & 1;

    const bf16 *Agh, *Agl;
    if (mode == 0) { Agh = g_Ahi + (size_t)mat*NROWS*ND; Agl = g_Alo + (size_t)mat*NROWS*ND; }
    else           { Agh = g_Ohi; Agl = g_Olo; }
    const int wmat = (mode == 0) ? mat : 2;
    const bf16* Wh = g_WThi + (size_t)wmat*ND*ND;
    const bf16* Wl = g_WTlo + (size_t)wmat*ND*ND;

    const uint32_t smb = smem_u32(sm);
#define GARR(s, a) (smb + (uint32_t)(((s)*4 + (a)) * 128 * KSTG * 2))

#define GEMM_LOAD(k0, s) do {                                                   \
    const bf16* _g0 = Agh + (size_t)(row0+lr)*ND + (k0) + lh*16;                \
    const bf16* _g1 = Agl + (size_t)(row0+lr)*ND + (k0) + lh*16;                \
    const bf16* _g2 = Wh  + (size_t)(col0+lr)*ND + (k0) + lh*16;                \
    const bf16* _g3 = Wl  + (size_t)(col0+lr)*ND + (k0) + lh*16;                \
    uint32_t _sd = (uint32_t)(lr*KSTG + lh*16)*2;                               \
    CPA(GARR(s,0) + _sd,      _g0);     CPA(GARR(s,0) + _sd + 16, _g0 + 8);     \
    CPA(GARR(s,1) + _sd,      _g1);     CPA(GARR(s,1) + _sd + 16, _g1 + 8);     \
    CPA(GARR(s,2) + _sd,      _g2);     CPA(GARR(s,2) + _sd + 16, _g2 + 8);     \
    CPA(GARR(s,3) + _sd,      _g3);     CPA(GARR(s,3) + _sd + 16, _g3 + 8);     \
    } while (0)

    float acc[4][4][4] = {};

    GEMM_LOAD(0, 0);  CPCOMMIT();
    GEMM_LOAD(32, 1); CPCOMMIT();

    for (int c = 0; c < 16; c++) {
        const int s = c & 1;
        if (c < 15) CPWAIT(1); else CPWAIT(0);
        __syncthreads();

        #pragma unroll
        for (int kf = 0; kf < 2; kf++) {
            uint32_t ah[4][4], al[4][4];
            #pragma unroll
            for (int mf = 0; mf < 4; mf++) {
                uint32_t r = wm*64 + mf*16 + (G & 1)*8 + rr;
                uint32_t cc = kf*16 + (G >> 1)*8;
                ldsm4(ah[mf], GARR(s,0) + (r*KSTG + cc)*2);
                ldsm4(al[mf], GARR(s,1) + (r*KSTG + cc)*2);
            }
            uint32_t bhv[2][4], blv[2][4];
            #pragma unroll
            for (int n2 = 0; n2 < 2; n2++) {
                uint32_t r = wn*32 + n2*16 + (G >> 1)*8 + rr;
                uint32_t cc = kf*16 + (G & 1)*8;
                ldsm4(bhv[n2], GARR(s,2) + (r*KSTG + cc)*2);
                ldsm4(blv[n2], GARR(s,3) + (r*KSTG + cc)*2);
            }
            #pragma unroll
            for (int mf = 0; mf < 4; mf++)
                #pragma unroll
                for (int nf = 0; nf < 4; nf++) {
                    const uint32_t* bh2 = &bhv[nf>>1][(nf&1)*2];
                    const uint32_t* bl2 = &blv[nf>>1][(nf&1)*2];
                    mma16816(acc[mf][nf], ah[mf], bh2);
                    mma16816(acc[mf][nf], ah[mf], bl2);
                    mma16816(acc[mf][nf], al[mf], bh2);
                }
        }
        __syncthreads();
        if (c + 2 < 16) { GEMM_LOAD((c+2)*32, s); CPCOMMIT(); }
    }

    #pragma unroll
    for (int mf = 0; mf < 4; mf++)
        #pragma unroll
        for (int nf = 0; nf < 4; nf++) {
            const int cc = col0 + wn*32 + nf*8 + tg*2;
            #pragma unroll
            for (int rr2 = 0; rr2 < 2; rr2++) {
                const int r = row0 + wm*64 + mf*16 + g + rr2*8;
                float x0 = acc[mf][nf][rr2*2], x1 = acc[mf][nf][rr2*2+1];
                if (mode == 0) {
                    int b = r >> 11, sN = r & 2047, h = cc >> 6, d = cc & 63;
                    size_t idx = (((size_t)(b*NH + h))*NS + sN)*NHD + d;
                    if (mat == 0)      *(uint32_t*)&g_Qf16[idx] = packh(x0, x1);
                    else if (mat == 1) *(uint32_t*)&g_Kf16[idx] = packh(x0, x1);
                    else {
                        *(uint32_t*)&g_Vf16[idx] = packh(x0, x1);
                        float h0 = __bfloat162float(__float2bfloat16(x0));
                        float h1 = __bfloat162float(__float2bfloat16(x1));
                        *(uint32_t*)&g_Vhi[idx] = packb(x0, x1);
                        *(uint32_t*)&g_Vlo[idx] = packb(x0 - h0, x1 - h1);
                    }
                } else {
                    *(float2*)&outp[(size_t)r*ND + cc] = make_float2(x0, x1);
                }
            }
        }
}

// ---------------- attention: fp16 single-term S and P'V ---------------------
// O_unnorm = Vsum(exact fp32) + P'@V, P' = expm1(relu(s/8)).
// smem: 4 stages x 2 arrays (K,V fp16) x 64 x KSTA = 73728. 2 CTAs/SM.
#define ATTN_SMEM (ASTG*2*64*KSTA*2)
__global__ __launch_bounds__(256, 2) void attn_kernel()
{
    extern __shared__ __half smh[];
    const int t = threadIdx.x, w = t >> 5, lane = t & 31;
    const int g = lane >> 2, tg = lane & 3;
    const int G = lane >> 3, rr = lane & 7;
    const int bh = blockIdx.y, q0 = blockIdx.x * 128;
    const size_t base = (size_t)bh * NS * NHD;
    const int alr = t >> 2, alc = (t & 3) * 16;

    const uint32_t smb = smem_u32(smh);
#define AARR(s, a) (smb + (uint32_t)(((s)*2 + (a)) * 64 * KSTA * 2))

#define ATTN_LOAD(j0, s) do {                                                   \
    const __half* _g0 = g_Kf16 + base + (size_t)((j0)+alr)*NHD + alc;           \
    const __half* _g1 = g_Vf16 + base + (size_t)((j0)+alr)*NHD + alc;           \
    uint32_t _sd = (uint32_t)(alr*KSTA + alc)*2;                                \
    CPA(AARR(s,0) + _sd,      _g0);     CPA(AARR(s,0) + _sd + 16, _g0 + 8);     \
    CPA(AARR(s,1) + _sd,      _g1);     CPA(AARR(s,1) + _sd + 16, _g1 + 8);     \
    } while (0)

    // ---- stage Q (128 rows fp16) through stage-0 arrays, extract frags -----
    {
        const int qlr = t >> 1, qlh = t & 1;
        const __half* q_g = g_Qf16 + base + (size_t)(q0+qlr)*NHD + qlh*32;
        uint32_t qd = AARR(0, qlr>>6) + (uint32_t)((qlr&63)*KSTA + qlh*32)*2;
        #pragma unroll
        for (int v = 0; v < 4; v++) CPA(qd + v*16, q_g + v*8);
        CPCOMMIT();
    }
    CPWAIT(0);
    __syncthreads();

    uint32_t qf[4][4];
    {
        const uint32_t r = w*16 + (G & 1)*8 + rr;
        const uint32_t arr = r >> 6, ir = r & 63;
        #pragma unroll
        for (int kf = 0; kf < 4; kf++) {
            uint32_t cc = kf*16 + (G >> 1)*8;
            ldsm4(qf[kf], AARR(0, arr) + (ir*KSTA + cc)*2);   // FIXED: *2 applies to whole offset
        }
    }
    __syncthreads();   // all warps done reading Q from stage 0

    ATTN_LOAD(0, 0);   CPCOMMIT();
    ATTN_LOAD(64, 1);  CPCOMMIT();
    ATTN_LOAD(128, 2); CPCOMMIT();

    float oacc[8][4] = {};
    float lsA[2][2] = {};

    for (int j = 0; j < 32; j++) {
        const int s = j & 3;
        if (j <= 29) CPWAIT(2); else if (j == 30) CPWAIT(1); else CPWAIT(0);
        __syncthreads();                            // tile j visible; stage (j-1)%4 free
        if (j + 3 < 32) { ATTN_LOAD((j+3)*64, (j+3) & 3); CPCOMMIT(); }

        // ---- S = Q @ K^T (single fp16 MMA) ----
        float c[8][4] = {};
        #pragma unroll
        for (int kf = 0; kf < 4; kf++) {
            #pragma unroll
            for (int n2 = 0; n2 < 4; n2++) {
                uint32_t brow = n2*16 + (G >> 1)*8 + rr;
                uint32_t bcol = kf*16 + (G & 1)*8;
                uint32_t kb[4];
                ldsm4(kb, AARR(s,0) + (brow*KSTA + bcol)*2);
                mma16816h(c[n2*2],   qf[kf], &kb[0]);
                mma16816h(c[n2*2+1], qf[kf], &kb[2]);
            }
        }
        // ---- P' = expm1(relu(s/8)); split-accumulate row sums ----
        #pragma unroll
        for (int nf = 0; nf < 8; nf++)
            #pragma unroll
            for (int i = 0; i < 4; i++) {
                float p = __expf(fmaxf(c[nf][i]*0.125f, 0.f)) - 1.0f;
                c[nf][i] = p;
                lsA[i>>1][nf&1] += p;
            }
        // ---- pack P' to fp16 (C-frag layout == A-frag layout) ----
        uint32_t pf[4][4];
        #pragma unroll
        for (int kq = 0; kq < 4; kq++)
            #pragma unroll
            for (int half = 0; half < 2; half++) {
                const float* cv = c[2*kq + half];
                pf[kq][2*half+0] = packh(cv[0], cv[1]);
                pf[kq][2*half+1] = packh(cv[2], cv[3]);
            }
        // ---- O += P' @ V (fp16, ldmatrix.trans) ----
        #pragma unroll
        for (int kq = 0; kq < 4; kq++) {
            #pragma unroll
            for (int d2 = 0; d2 < 4; d2++) {
                uint32_t vrow = kq*16 + (G & 1)*8 + rr;
                uint32_t vcol = d2*16 + (G >> 1)*8;
                uint32_t vb[4];
                ldsm4t(vb, AARR(s,1) + (vrow*KSTA + vcol)*2);
                mma16816h(oacc[d2*2],   pf[kq], &vb[0]);
                mma16816h(oacc[d2*2+1], pf[kq], &vb[2]);
            }
        }
    }

    float lsum[2] = { lsA[0][0] + lsA[0][1], lsA[1][0] + lsA[1][1] };
    #pragma unroll
    for (int i = 0; i < 2; i++) {
        lsum[i] += __shfl_xor_sync(0xffffffffu, lsum[i], 1);
        lsum[i] += __shfl_xor_sync(0xffffffffu, lsum[i], 2);
    }
    const float inv0 = 1.f / (2048.f + lsum[0]);
    const float inv1 = 1.f / (2048.f + lsum[1]);

    const int b = bh >> 3, h = bh & 7;
    const float* vs = &g_Vsum[bh*64];
    #pragma unroll
    for (int nf = 0; nf < 8; nf++) {
        const int d = nf*8 + tg*2;
        const int col = h*NHD + d;
        const float2 v2 = *(const float2*)&vs[d];
        #pragma unroll
        for (int rr2 = 0; rr2 < 2; rr2++) {
            const int srow = q0 + w*16 + g + rr2*8;
            const float inv = rr2 ? inv1 : inv0;
            float x0 = (oacc[nf][rr2*2]   + v2.x) * inv;
            float x1 = (oacc[nf][rr2*2+1] + v2.y) * inv;
            float h0 = __bfloat162float(__float2bfloat16(x0));
            float h1 = __bfloat162float(__float2bfloat16(x1));
            size_t idx = ((size_t)(b*NS + srow))*ND + col;
            *(uint32_t*)&g_Ohi[idx] = packb(x0, x1);
            *(uint32_t*)&g_Olo[idx] = packb(x0 - h0, x1 - h1);
        }
    }
}

// ---------------------------------------------------------------------------
extern "C" void kernel_launch(void* const* d_in, const int* in_sizes, int n_in,
                              void* d_out, int out_size)
{
    const float* X  = (const float*)d_in[0];
    const float* Y  = (const float*)d_in[1];
    const float* Z  = (const float*)d_in[2];
    const float* Wq = (const float*)d_in[3];
    const float* Wk = (const float*)d_in[4];
    /* d_in[5] = Wv unused (reference uses Wo for V projection) */
    const float* Wo = (const float*)d_in[6];
    float* out = (float*)d_out;

    static bool attr_done = false;
    if (!attr_done) {
        cudaFuncSetAttribute(mma_gemm,    cudaFuncAttributeMaxDynamicSharedMemorySize, GEMM_SMEM);
        cudaFuncSetAttribute(attn_kernel, cudaFuncAttributeMaxDynamicSharedMemorySize, ATTN_SMEM);
        attr_done = true;
    }

    convert_wt<<<dim3(16, 16, 3), 256>>>(Wq, Wk, Wo);
    convert_act<<<NROWS*ND/4/256, 256>>>((const float4*)X, 0);
    convert_act<<<NROWS*ND/4/256, 256>>>((const float4*)Y, 1);
    convert_act<<<NROWS*ND/4/256, 256>>>((const float4*)Z, 2);
    mma_gemm<<<dim3(4, 64, 3), 256, GEMM_SMEM>>>(nullptr, 0);   // Q,K,V projections
    vsum_kernel<<<32, 256>>>();                                  // exact V column sums
    attn_kernel<<<dim3(16, 32), 256, ATTN_SMEM>>>();             // fused attention
    mma_gemm<<<dim3(4, 64, 1), 256, GEMM_SMEM>>>(out, 1);        // O @ Wo
}

// round 16
// speedup vs baseline: 7.0029x; 1.4979x over previous
#include <cuda_runtime.h>
#include <cuda_bf16.h>
#include <cuda_fp16.h>
#include <cstdint>

#define NB  4
#define NS  2048
#define ND  512
#define NH  8
#define NHD 64
#define NROWS (NB*NS)   // 8192
#define KSTA 72         // attn smem row stride (144B) — ldmatrix conflict-free
#define KSTG 40         // gemm smem row stride (80B)  — ldmatrix conflict-free
#define ASTG 4          // attn pipeline stages
#define GSTG 4          // gemm pipeline stages

// ---------------- device-global scratch (all fp16 now) ----------------------
__device__ __half g_Af16[3ull*NROWS*ND];      // X,Y,Z fp16
__device__ __half g_WTf16[3ull*ND*ND];        // Wq^T, Wk^T, Wo^T fp16
__device__ __half g_Qf16[(size_t)NROWS*ND];   // [B,H,S,64]
__device__ __half g_Kf16[(size_t)NROWS*ND];
__device__ __half g_Vf16[(size_t)NROWS*ND];
__device__ __half g_Of16[(size_t)NROWS*ND];   // merged [B,S,D]
__device__ float  g_Vsum[NB*NH*NHD];

// ---------------- helpers ----------------------------------------------------
__device__ __forceinline__ void mma16816h(float c[4], const uint32_t a[4], const uint32_t b[2]) {
    asm volatile("mma.sync.aligned.m16n8k16.row.col.f32.f16.f16.f32 "
        "{%0,%1,%2,%3}, {%4,%5,%6,%7}, {%8,%9}, {%0,%1,%2,%3};"
        : "+f"(c[0]), "+f"(c[1]), "+f"(c[2]), "+f"(c[3])
        : "r"(a[0]), "r"(a[1]), "r"(a[2]), "r"(a[3]), "r"(b[0]), "r"(b[1]));
}
__device__ __forceinline__ uint32_t packh(float x, float y) {
    __half2 h = __floats2half2_rn(x, y);
    return *(uint32_t*)&h;
}
__device__ __forceinline__ uint32_t smem_u32(const void* p) {
    uint32_t a;
    asm("{ .reg .u64 t; cvta.to.shared.u64 t, %1; cvt.u32.u64 %0, t; }" : "=r"(a) : "l"(p));
    return a;
}
__device__ __forceinline__ void ldsm4(uint32_t r[4], uint32_t addr) {
    asm volatile("ldmatrix.sync.aligned.m8n8.x4.shared.b16 {%0,%1,%2,%3}, [%4];"
        : "=r"(r[0]), "=r"(r[1]), "=r"(r[2]), "=r"(r[3]) : "r"(addr));
}
__device__ __forceinline__ void ldsm4t(uint32_t r[4], uint32_t addr) {
    asm volatile("ldmatrix.sync.aligned.m8n8.x4.trans.shared.b16 {%0,%1,%2,%3}, [%4];"
        : "=r"(r[0]), "=r"(r[1]), "=r"(r[2]), "=r"(r[3]) : "r"(addr));
}
#define CPA(sd, gs) \
    asm volatile("cp.async.cg.shared.global [%0], [%1], 16;" :: "r"(sd), "l"(gs) : "memory")
#define CPCOMMIT() asm volatile("cp.async.commit_group;" ::: "memory")
#define CPWAIT(n)  asm volatile("cp.async.wait_group %0;" :: "n"(n) : "memory")

// ---------------- converts ---------------------------------------------------
// fp32 act -> fp16; handles two matrices per launch via blockIdx.y
__global__ __launch_bounds__(256) void convert_act(
    const float4* __restrict__ srcA, const float4* __restrict__ srcB, int whichA, int whichB)
{
    size_t i = (size_t)blockIdx.x * 256 + threadIdx.x;
    const float4* src = (blockIdx.y == 0) ? srcA : srcB;
    int which = (blockIdx.y == 0) ? whichA : whichB;
    __half* dst = g_Af16 + (size_t)which*NROWS*ND;
    float4 v = src[i];
    ushort2 a, b;
    *(uint32_t*)&a = packh(v.x, v.y);
    *(uint32_t*)&b = packh(v.z, v.w);
    *(ushort4*)((unsigned short*)dst + 4*i) = make_ushort4(a.x, a.y, b.x, b.y);
}
// coalesced W -> WT transpose, fp16, all 3 mats
__global__ __launch_bounds__(256) void convert_wt(
    const float* __restrict__ Wq, const float* __restrict__ Wk, const float* __restrict__ Wo)
{
    __shared__ float tile[32][33];
    const int z = blockIdx.z;
    const float* W = (z == 0) ? Wq : (z == 1) ? Wk : Wo;
    const int tx = threadIdx.x & 31, ty = threadIdx.x >> 5;
    const int x0 = blockIdx.x * 32, y0 = blockIdx.y * 32;
    #pragma unroll
    for (int i = ty; i < 32; i += 8)
        tile[i][tx] = W[(size_t)(y0 + i) * ND + x0 + tx];
    __syncthreads();
    __half* dst = g_WTf16 + (size_t)z*ND*ND;
    #pragma unroll
    for (int i = ty; i < 32; i += 8)
        dst[(size_t)(x0 + i) * ND + y0 + tx] = __float2half_rn(tile[tx][i]);
}

// fp32 column-sums of fp16 V per (b,h)
__global__ __launch_bounds__(256) void vsum_kernel()
{
    __shared__ float acc[4][64];
    const int bh = blockIdx.x;
    const int d = threadIdx.x & 63, q = threadIdx.x >> 6;
    const __half* v = g_Vf16 + (size_t)bh*NS*NHD;
    float s = 0.f;
    for (int i = q*512; i < q*512 + 512; i++)
        s += __half2float(v[(size_t)i*NHD + d]);
    acc[q][d] = s;
    __syncthreads();
    if (q == 0)
        g_Vsum[bh*64 + d] = acc[0][d] + acc[1][d] + acc[2][d] + acc[3][d];
}

// ---------------- fp16 GEMM: C[8192,512] = A @ W -----------------------------
// 128x128 block tile, 8 warps (2m x 4n), k-chunks of 32, 4-stage single-sync.
// smem = 4 stages x 2 arrays x 128 x KSTG x 2B = 81920 -> 2 CTAs/SM.
#define GEMM_SMEM (GSTG*2*128*KSTG*2)
__global__ __launch_bounds__(256, 2) void mma_gemm(float* __restrict__ outp, int mode)
{
    extern __shared__ __half smg[];
    const int t = threadIdx.x, w = t >> 5, lane = t & 31;
    const int g = lane >> 2, tg = lane & 3;
    const int G = lane >> 3, rr = lane & 7;
    const int wm = w >> 2, wn = w & 3;
    const int row0 = blockIdx.y * 128, col0 = blockIdx.x * 128;
    const int mat = blockIdx.z;
    const int lr = t >> 1, lh = t & 1;   // loader: row 0..127, 16-col half

    const __half* Ag = (mode == 0) ? g_Af16 + (size_t)mat*NROWS*ND : g_Of16;
    const __half* Wg = g_WTf16 + (size_t)((mode == 0) ? mat : 2)*ND*ND;

    const uint32_t smb = smem_u32(smg);
#define GARR(s, a) (smb + (uint32_t)(((s)*2 + (a)) * 128 * KSTG * 2))

#define GEMM_LOAD(k0, s) do {                                                   \
    const __half* _g0 = Ag + (size_t)(row0+lr)*ND + (k0) + lh*16;               \
    const __half* _g1 = Wg + (size_t)(col0+lr)*ND + (k0) + lh*16;               \
    uint32_t _sd = (uint32_t)(lr*KSTG + lh*16)*2;                               \
    CPA(GARR(s,0) + _sd,      _g0);     CPA(GARR(s,0) + _sd + 16, _g0 + 8);     \
    CPA(GARR(s,1) + _sd,      _g1);     CPA(GARR(s,1) + _sd + 16, _g1 + 8);     \
    } while (0)

    float acc[4][4][4] = {};

    GEMM_LOAD(0, 0);  CPCOMMIT();
    GEMM_LOAD(32, 1); CPCOMMIT();
    GEMM_LOAD(64, 2); CPCOMMIT();

    for (int c = 0; c < 16; c++) {
        const int s = c & 3;
        if (c <= 13) CPWAIT(2); else if (c == 14) CPWAIT(1); else CPWAIT(0);
        __syncthreads();                        // chunk c resident; stage (c-1)&3 free
        if (c + 3 < 16) { GEMM_LOAD((c+3)*32, (c+3) & 3); CPCOMMIT(); }

        #pragma unroll
        for (int kf = 0; kf < 2; kf++) {
            uint32_t ah[4][4];
            #pragma unroll
            for (int mf = 0; mf < 4; mf++) {
                uint32_t r = wm*64 + mf*16 + (G & 1)*8 + rr;
                uint32_t cc = kf*16 + (G >> 1)*8;
                ldsm4(ah[mf], GARR(s,0) + (r*KSTG + cc)*2);
            }
            uint32_t bv[2][4];
            #pragma unroll
            for (int n2 = 0; n2 < 2; n2++) {
                uint32_t r = wn*32 + n2*16 + (G >> 1)*8 + rr;
                uint32_t cc = kf*16 + (G & 1)*8;
                ldsm4(bv[n2], GARR(s,1) + (r*KSTG + cc)*2);
            }
            #pragma unroll
            for (int mf = 0; mf < 4; mf++)
                #pragma unroll
                for (int nf = 0; nf < 4; nf++)
                    mma16816h(acc[mf][nf], ah[mf], &bv[nf>>1][(nf&1)*2]);
        }
    }

    #pragma unroll
    for (int mf = 0; mf < 4; mf++)
        #pragma unroll
        for (int nf = 0; nf < 4; nf++) {
            const int cc = col0 + wn*32 + nf*8 + tg*2;
            #pragma unroll
            for (int rr2 = 0; rr2 < 2; rr2++) {
                const int r = row0 + wm*64 + mf*16 + g + rr2*8;
                float x0 = acc[mf][nf][rr2*2], x1 = acc[mf][nf][rr2*2+1];
                if (mode == 0) {
                    int b = r >> 11, sN = r & 2047, h = cc >> 6, d = cc & 63;
                    size_t idx = (((size_t)(b*NH + h))*NS + sN)*NHD + d;
                    uint32_t p = packh(x0, x1);
                    if (mat == 0)      *(uint32_t*)&g_Qf16[idx] = p;
                    else if (mat == 1) *(uint32_t*)&g_Kf16[idx] = p;
                    else               *(uint32_t*)&g_Vf16[idx] = p;
                } else {
                    *(float2*)&outp[(size_t)r*ND + cc] = make_float2(x0, x1);
                }
            }
        }
}

// ---------------- attention: fp16 single-term S and P'V ---------------------
// O_unnorm = Vsum(fp32) + P'@V, P' = expm1(relu(s/8)).
// smem: 4 stages x 2 arrays (K,V fp16) x 64 x KSTA = 73728. 2 CTAs/SM.
#define ATTN_SMEM (ASTG*2*64*KSTA*2)
__global__ __launch_bounds__(256, 2) void attn_kernel()
{
    extern __shared__ __half smh[];
    const int t = threadIdx.x, w = t >> 5, lane = t & 31;
    const int g = lane >> 2, tg = lane & 3;
    const int G = lane >> 3, rr = lane & 7;
    const int bh = blockIdx.y, q0 = blockIdx.x * 128;
    const size_t base = (size_t)bh * NS * NHD;
    const int alr = t >> 2, alc = (t & 3) * 16;

    const uint32_t smb = smem_u32(smh);
#define AARR(s, a) (smb + (uint32_t)(((s)*2 + (a)) * 64 * KSTA * 2))

#define ATTN_LOAD(j0, s) do {                                                   \
    const __half* _g0 = g_Kf16 + base + (size_t)((j0)+alr)*NHD + alc;           \
    const __half* _g1 = g_Vf16 + base + (size_t)((j0)+alr)*NHD + alc;           \
    uint32_t _sd = (uint32_t)(alr*KSTA + alc)*2;                                \
    CPA(AARR(s,0) + _sd,      _g0);     CPA(AARR(s,0) + _sd + 16, _g0 + 8);     \
    CPA(AARR(s,1) + _sd,      _g1);     CPA(AARR(s,1) + _sd + 16, _g1 + 8);     \
    } while (0)

    // ---- stage Q (128 rows fp16) through stage-0 arrays, extract frags -----
    {
        const int qlr = t >> 1, qlh = t & 1;
        const __half* q_g = g_Qf16 + base + (size_t)(q0+qlr)*NHD + qlh*32;
        uint32_t qd = AARR(0, qlr>>6) + (uint32_t)((qlr&63)*KSTA + qlh*32)*2;
        #pragma unroll
        for (int v = 0; v < 4; v++) CPA(qd + v*16, q_g + v*8);
        CPCOMMIT();
    }
    CPWAIT(0);
    __syncthreads();

    uint32_t qf[4][4];
    {
        const uint32_t r = w*16 + (G & 1)*8 + rr;
        const uint32_t arr = r >> 6, ir = r & 63;
        #pragma unroll
        for (int kf = 0; kf < 4; kf++) {
            uint32_t cc = kf*16 + (G >> 1)*8;
            ldsm4(qf[kf], AARR(0, arr) + (ir*KSTA + cc)*2);
        }
    }
    __syncthreads();   // all warps done reading Q from stage 0

    ATTN_LOAD(0, 0);   CPCOMMIT();
    ATTN_LOAD(64, 1);  CPCOMMIT();
    ATTN_LOAD(128, 2); CPCOMMIT();

    float oacc[8][4] = {};
    float lsA[2][2] = {};

    for (int j = 0; j < 32; j++) {
        const int s = j & 3;
        if (j <= 29) CPWAIT(2); else if (j == 30) CPWAIT(1); else CPWAIT(0);
        __syncthreads();                            // tile j visible; stage (j-1)%4 free
        if (j + 3 < 32) { ATTN_LOAD((j+3)*64, (j+3) & 3); CPCOMMIT(); }

        // ---- S = Q @ K^T (single fp16 MMA) ----
        float c[8][4] = {};
        #pragma unroll
        for (int kf = 0; kf < 4; kf++) {
            #pragma unroll
            for (int n2 = 0; n2 < 4; n2++) {
                uint32_t brow = n2*16 + (G >> 1)*8 + rr;
                uint32_t bcol = kf*16 + (G & 1)*8;
                uint32_t kb[4];
                ldsm4(kb, AARR(s,0) + (brow*KSTA + bcol)*2);
                mma16816h(c[n2*2],   qf[kf], &kb[0]);
                mma16816h(c[n2*2+1], qf[kf], &kb[2]);
            }
        }
        // ---- P' = expm1(relu(s/8)); split-accumulate row sums ----
        #pragma unroll
        for (int nf = 0; nf < 8; nf++)
            #pragma unroll
            for (int i = 0; i < 4; i++) {
                float p = __expf(fmaxf(c[nf][i]*0.125f, 0.f)) - 1.0f;
                c[nf][i] = p;
                lsA[i>>1][nf&1] += p;
            }
        // ---- pack P' to fp16 (C-frag layout == A-frag layout) ----
        uint32_t pf[4][4];
        #pragma unroll
        for (int kq = 0; kq < 4; kq++)
            #pragma unroll
            for (int half = 0; half < 2; half++) {
                const float* cv = c[2*kq + half];
                pf[kq][2*half+0] = packh(cv[0], cv[1]);
                pf[kq][2*half+1] = packh(cv[2], cv[3]);
            }
        // ---- O += P' @ V (fp16, ldmatrix.trans) ----
        #pragma unroll
        for (int kq = 0; kq < 4; kq++) {
            #pragma unroll
            for (int d2 = 0; d2 < 4; d2++) {
                uint32_t vrow = kq*16 + (G & 1)*8 + rr;
                uint32_t vcol = d2*16 + (G >> 1)*8;
                uint32_t vb[4];
                ldsm4t(vb, AARR(s,1) + (vrow*KSTA + vcol)*2);
                mma16816h(oacc[d2*2],   pf[kq], &vb[0]);
                mma16816h(oacc[d2*2+1], pf[kq], &vb[2]);
            }
        }
    }

    float lsum[2] = { lsA[0][0] + lsA[0][1], lsA[1][0] + lsA[1][1] };
    #pragma unroll
    for (int i = 0; i < 2; i++) {
        lsum[i] += __shfl_xor_sync(0xffffffffu, lsum[i], 1);
        lsum[i] += __shfl_xor_sync(0xffffffffu, lsum[i], 2);
    }
    const float inv0 = 1.f / (2048.f + lsum[0]);
    const float inv1 = 1.f / (2048.f + lsum[1]);

    const int b = bh >> 3, h = bh & 7;
    const float* vs = &g_Vsum[bh*64];
    #pragma unroll
    for (int nf = 0; nf < 8; nf++) {
        const int d = nf*8 + tg*2;
        const int col = h*NHD + d;
        const float2 v2 = *(const float2*)&vs[d];
        #pragma unroll
        for (int rr2 = 0; rr2 < 2; rr2++) {
            const int srow = q0 + w*16 + g + rr2*8;
            const float inv = rr2 ? inv1 : inv0;
            float x0 = (oacc[nf][rr2*2]   + v2.x) * inv;
            float x1 = (oacc[nf][rr2*2+1] + v2.y) * inv;
            size_t idx = ((size_t)(b*NS + srow))*ND + col;
            *(uint32_t*)&g_Of16[idx] = packh(x0, x1);
        }
    }
}

// ---------------------------------------------------------------------------
extern "C" void kernel_launch(void* const* d_in, const int* in_sizes, int n_in,
                              void* d_out, int out_size)
{
    const float* X  = (const float*)d_in[0];
    const float* Y  = (const float*)d_in[1];
    const float* Z  = (const float*)d_in[2];
    const float* Wq = (const float*)d_in[3];
    const float* Wk = (const float*)d_in[4];
    /* d_in[5] = Wv unused (reference uses Wo for V projection) */
    const float* Wo = (const float*)d_in[6];
    float* out = (float*)d_out;

    static bool attr_done = false;
    if (!attr_done) {
        cudaFuncSetAttribute(mma_gemm,    cudaFuncAttributeMaxDynamicSharedMemorySize, GEMM_SMEM);
        cudaFuncSetAttribute(attn_kernel, cudaFuncAttributeMaxDynamicSharedMemorySize, ATTN_SMEM);
        attr_done = true;
    }

    // launch order keeps attn_kernel at ncu index 5
    convert_wt<<<dim3(16, 16, 3), 256>>>(Wq, Wk, Wo);                          // 0
    convert_act<<<dim3(NROWS*ND/4/256, 2), 256>>>(
        (const float4*)X, (const float4*)Y, 0, 1);                            // 1
    convert_act<<<dim3(NROWS*ND/4/256, 1), 256>>>(
        (const float4*)Z, (const float4*)Z, 2, 2);                            // 2
    mma_gemm<<<dim3(4, 64, 3), 256, GEMM_SMEM>>>(nullptr, 0);                  // 3
    vsum_kernel<<<32, 256>>>();                                                // 4
    attn_kernel<<<dim3(16, 32), 256, ATTN_SMEM>>>();                           // 5 <- profiled
    mma_gemm<<<dim3(4, 64, 1), 256, GEMM_SMEM>>>(out, 1);                      // 6
}